// round 3
// baseline (speedup 1.0000x reference)
#include <cuda_runtime.h>
#include <cstdint>

#define SLOPE 0.15f

static const int NN = 50000;   // nodes (fixed by problem)

// ---------------- device scratch (no runtime allocation allowed) -------------
__device__ float g_cntinv[NN];                 // 1/max(deg,1)
__device__ float g_agg  [NN * 256];            // segment-sum buffer (max dim 256)
__device__ float g_h1   [NN * 512];
__device__ float g_z2   [NN * 256];
__device__ float g_r2   [NN * 256];
__device__ float g_h2   [NN * 256];
__device__ float g_z3   [NN * 64];
__device__ float g_r3   [NN * 64];
__device__ float g_h3   [NN * 64];

// ---------------- small utility kernels --------------------------------------
__global__ void zero4_kernel(float* __restrict__ p, int n4) {
    int i = blockIdx.x * blockDim.x + threadIdx.x;
    if (i < n4) ((float4*)p)[i] = make_float4(0.f, 0.f, 0.f, 0.f);
}

__global__ void count_kernel(const int* __restrict__ dst, float* __restrict__ cnt, int ne) {
    int e = blockIdx.x * blockDim.x + threadIdx.x;
    if (e < ne) atomicAdd(&cnt[dst[e]], 1.0f);
}

__global__ void invert_kernel(float* __restrict__ c, int n) {
    int i = blockIdx.x * blockDim.x + threadIdx.x;
    if (i < n) c[i] = 1.0f / fmaxf(c[i], 1.0f);
}

// vectorized global reduction add (sm_90+)
__device__ __forceinline__ void red_add_v4(float* addr, float4 v) {
    asm volatile("red.global.add.v4.f32 [%0], {%1,%2,%3,%4};"
                 :: "l"(addr), "f"(v.x), "f"(v.y), "f"(v.z), "f"(v.w) : "memory");
}

// segment-sum: out[dst] += feat[src] over edges, d4 = dim/4
__global__ void agg_kernel(const float* __restrict__ feat, const int* __restrict__ src,
                           const int* __restrict__ dst, float* __restrict__ out,
                           int d4, int ne) {
    long long idx = (long long)blockIdx.x * blockDim.x + threadIdx.x;
    long long total = (long long)ne * d4;
    if (idx >= total) return;
    int e = (int)(idx / d4);
    int c = (int)(idx % d4);
    int s = src[e], d = dst[e];
    float4 v = *(const float4*)(feat + (size_t)s * d4 * 4 + c * 4);
    red_add_v4(out + (size_t)d * d4 * 4 + c * 4, v);
}

// h = leaky(agg*inv + bias + r)
__global__ void ew_kernel(const float* __restrict__ agg, const float* __restrict__ inv,
                          const float* __restrict__ r, const float* __restrict__ bias,
                          float* __restrict__ out, int d4, int n) {
    int idx = blockIdx.x * blockDim.x + threadIdx.x;
    if (idx >= n * d4) return;
    int row = idx / d4, c = idx % d4;
    float iv = inv[row];
    float4 a = ((const float4*)agg)[idx];
    float4 rr = ((const float4*)r)[idx];
    float4 b = ((const float4*)bias)[c];
    float4 o;
    o.x = fmaf(a.x, iv, b.x) + rr.x;
    o.y = fmaf(a.y, iv, b.y) + rr.y;
    o.z = fmaf(a.z, iv, b.z) + rr.z;
    o.w = fmaf(a.w, iv, b.w) + rr.w;
    o.x = o.x > 0.f ? o.x : SLOPE * o.x;
    o.y = o.y > 0.f ? o.y : SLOPE * o.y;
    o.z = o.z > 0.f ? o.z : SLOPE * o.z;
    o.w = o.w > 0.f ? o.w : SLOPE * o.w;
    ((float4*)out)[idx] = o;
}

// ---------------- compute-bound f32x2 GEMM ------------------------------------
// Tile 128(M) x 128(N) x 8(K), 256 threads, 8x8 per thread = 32 FFMA2/k.
// A and B stored UNduplicated in smem (64B LDS per thread per k, a-loads are
// warp broadcasts). {a,a} broadcast operands built in registers on the ALU pipe.

#define GBM 128
#define GBN 128
#define GBK 8
#define ASTR 132    // padded k-row stride for As (avoids STS bank conflicts)
#define BSTR 128

#define FLAG_CONCAT 1  // K split: A=[A1(scaled by cntinv) | A2], B=[B1;B2] row blocks
#define FLAG_NCAT   2  // N split: B=[B1|B2], C=[C1|C2], each Nh=N/2 wide
#define FLAG_BIAS   4
#define FLAG_LEAKY  8

__device__ __forceinline__ void fma2(unsigned long long &d, unsigned long long a, unsigned long long b) {
    asm("fma.rn.f32x2 %0, %1, %2, %0;" : "+l"(d) : "l"(a), "l"(b));
}
__device__ __forceinline__ unsigned long long dup2(float a) {
    unsigned long long r;
    unsigned ai = __float_as_uint(a);
    asm("mov.b64 %0, {%1, %1};" : "=l"(r) : "r"(ai));
    return r;
}
__device__ __forceinline__ float lo2(unsigned long long v) { return __uint_as_float((unsigned)v); }
__device__ __forceinline__ float hi2(unsigned long long v) { return __uint_as_float((unsigned)(v >> 32)); }

template<int FLAGS>
__global__ __launch_bounds__(256, 1) void gemm2_kernel(
    const float* __restrict__ A1, const float* __restrict__ A2, int K1,
    const float* __restrict__ cntinv,
    const float* __restrict__ B1, const float* __restrict__ B2,
    float* __restrict__ C1, float* __restrict__ C2,
    const float* __restrict__ bias,
    int M, int N, int K)
{
    __shared__ float As[GBK * ASTR];
    __shared__ float Bs[GBK * BSTR];

    const int tid = threadIdx.x;
    const int bm = blockIdx.y * GBM;
    const int bn = blockIdx.x * GBN;
    const int Nh = N >> 1;           // used only when FLAG_NCAT

    // compute mapping: 16x16 thread grid, 8x8 per thread
    const int tx = tid & 15;         // n block: bn + tx*8
    const int ty = tid >> 4;         // m block: bm + ty*8

    // A loader: 1 float4 per thread (m = tid>>1, k4 = (tid&1)*4)
    const int am  = tid >> 1;
    const int ak4 = (tid & 1) * 4;
    const int agm = bm + am;
    const bool aok = agm < M;
    const float ascale = ((FLAGS & FLAG_CONCAT) && aok) ? cntinv[agm] : 1.0f;

    // B loader: 1 float4 per thread (k = tid>>5, col = (tid&31)*4)
    const int bk  = tid >> 5;
    const int bc  = (tid & 31) * 4;

    const int K2 = K - K1;

    unsigned long long acc[8][4];
    #pragma unroll
    for (int i = 0; i < 8; i++)
        #pragma unroll
        for (int j = 0; j < 4; j++) acc[i][j] = 0ull;

    float4 av, bv;

    auto load_tile = [&](int k0) {
        // A
        {
            const float* src;
            bool first = true;
            if (FLAGS & FLAG_CONCAT) {
                if (k0 < K1) src = A1 + (size_t)agm * K1 + k0 + ak4;
                else { src = A2 + (size_t)agm * K2 + (k0 - K1) + ak4; first = false; }
            } else {
                src = A1 + (size_t)agm * K + k0 + ak4;
            }
            float4 v = make_float4(0.f, 0.f, 0.f, 0.f);
            if (aok) v = *(const float4*)src;
            if ((FLAGS & FLAG_CONCAT) && first) {
                v.x *= ascale; v.y *= ascale; v.z *= ascale; v.w *= ascale;
            }
            av = v;
        }
        // B
        {
            const float* src;
            int kg = k0 + bk;
            if (FLAGS & FLAG_CONCAT) {
                if (kg < K1) src = B1 + (size_t)kg * N + bn + bc;
                else         src = B2 + (size_t)(kg - K1) * N + bn + bc;
            } else if (FLAGS & FLAG_NCAT) {
                int c = bn + bc;
                if (c < Nh) src = B1 + (size_t)kg * Nh + c;
                else        src = B2 + (size_t)kg * Nh + (c - Nh);
            } else {
                src = B1 + (size_t)kg * N + bn + bc;
            }
            bv = *(const float4*)src;
        }
    };

    auto store_tile = [&]() {
        As[(ak4 + 0) * ASTR + am] = av.x;
        As[(ak4 + 1) * ASTR + am] = av.y;
        As[(ak4 + 2) * ASTR + am] = av.z;
        As[(ak4 + 3) * ASTR + am] = av.w;
        *(float4*)&Bs[bk * BSTR + bc] = bv;
    };

    load_tile(0);
    store_tile();
    __syncthreads();

    const int ktiles = K / GBK;
    for (int t = 0; t < ktiles; t++) {
        if (t + 1 < ktiles) load_tile((t + 1) * GBK);
        #pragma unroll
        for (int k = 0; k < GBK; k++) {
            float4 a0 = *(const float4*)&As[k * ASTR + ty * 8];
            float4 a1 = *(const float4*)&As[k * ASTR + ty * 8 + 4];
            ulonglong2 b01 = *(const ulonglong2*)&Bs[k * BSTR + tx * 8];
            ulonglong2 b23 = *(const ulonglong2*)&Bs[k * BSTR + tx * 8 + 4];
            unsigned long long pa[8];
            pa[0] = dup2(a0.x); pa[1] = dup2(a0.y); pa[2] = dup2(a0.z); pa[3] = dup2(a0.w);
            pa[4] = dup2(a1.x); pa[5] = dup2(a1.y); pa[6] = dup2(a1.z); pa[7] = dup2(a1.w);
            #pragma unroll
            for (int i = 0; i < 8; i++) {
                fma2(acc[i][0], pa[i], b01.x);
                fma2(acc[i][1], pa[i], b01.y);
                fma2(acc[i][2], pa[i], b23.x);
                fma2(acc[i][3], pa[i], b23.y);
            }
        }
        __syncthreads();
        if (t + 1 < ktiles) { store_tile(); __syncthreads(); }
    }

    // epilogue
    const int c0 = bn + tx * 8;
    const float* Cb; int cc; int cstride;
    float* Cout;
    if (FLAGS & FLAG_NCAT) {
        if (c0 < Nh) { Cout = C1; cc = c0; }
        else         { Cout = C2; cc = c0 - Nh; }
        cstride = Nh;
    } else {
        Cout = C1; cc = c0; cstride = N;
    }
    (void)Cb;

    float4 bb0 = make_float4(0.f,0.f,0.f,0.f), bb1 = bb0;
    if (FLAGS & FLAG_BIAS) {
        bb0 = *(const float4*)(bias + c0);
        bb1 = *(const float4*)(bias + c0 + 4);
    }
    #pragma unroll
    for (int i = 0; i < 8; i++) {
        int gm = bm + ty * 8 + i;
        if (gm >= M) continue;
        float4 v0 = make_float4(lo2(acc[i][0]), hi2(acc[i][0]), lo2(acc[i][1]), hi2(acc[i][1]));
        float4 v1 = make_float4(lo2(acc[i][2]), hi2(acc[i][2]), lo2(acc[i][3]), hi2(acc[i][3]));
        if (FLAGS & FLAG_BIAS) {
            v0.x += bb0.x; v0.y += bb0.y; v0.z += bb0.z; v0.w += bb0.w;
            v1.x += bb1.x; v1.y += bb1.y; v1.z += bb1.z; v1.w += bb1.w;
        }
        if (FLAGS & FLAG_LEAKY) {
            v0.x = v0.x > 0.f ? v0.x : SLOPE * v0.x;
            v0.y = v0.y > 0.f ? v0.y : SLOPE * v0.y;
            v0.z = v0.z > 0.f ? v0.z : SLOPE * v0.z;
            v0.w = v0.w > 0.f ? v0.w : SLOPE * v0.w;
            v1.x = v1.x > 0.f ? v1.x : SLOPE * v1.x;
            v1.y = v1.y > 0.f ? v1.y : SLOPE * v1.y;
            v1.z = v1.z > 0.f ? v1.z : SLOPE * v1.z;
            v1.w = v1.w > 0.f ? v1.w : SLOPE * v1.w;
        }
        float* crow = Cout + (size_t)gm * cstride + cc;
        *(float4*)crow       = v0;
        *(float4*)(crow + 4) = v1;
    }
}

// ---------------- fused head: h3[64] -> Wp(32) -> leaky(Wf1(32)) -> Wf2(2) ----
__global__ __launch_bounds__(128) void head_kernel(
    const float* __restrict__ h3,
    const float* __restrict__ Wp, const float* __restrict__ bp,
    const float* __restrict__ Wf1, const float* __restrict__ bf1,
    const float* __restrict__ Wf2, const float* __restrict__ bf2,
    float* __restrict__ out, int n)
{
    __shared__ float sWp[64 * 32], sWf1[32 * 32], sWf2[64], sbp[32], sbf1[32], sbf2[2];
    for (int i = threadIdx.x; i < 64 * 32; i += blockDim.x) sWp[i] = Wp[i];
    for (int i = threadIdx.x; i < 32 * 32; i += blockDim.x) sWf1[i] = Wf1[i];
    for (int i = threadIdx.x; i < 64; i += blockDim.x) sWf2[i] = Wf2[i];
    if (threadIdx.x < 32) { sbp[threadIdx.x] = bp[threadIdx.x]; sbf1[threadIdx.x] = bf1[threadIdx.x]; }
    if (threadIdx.x < 2) sbf2[threadIdx.x] = bf2[threadIdx.x];
    __syncthreads();
    int nidx = blockIdx.x * blockDim.x + threadIdx.x;
    if (nidx >= n) return;

    float p[32];
#pragma unroll
    for (int j = 0; j < 32; j++) p[j] = sbp[j];
    const float* hx = h3 + (size_t)nidx * 64;
    for (int i = 0; i < 64; i++) {
        float xi = hx[i];
#pragma unroll
        for (int j = 0; j < 32; j++) p[j] = fmaf(xi, sWp[i * 32 + j], p[j]);
    }
    float q[32];
#pragma unroll
    for (int j = 0; j < 32; j++) q[j] = sbf1[j];
#pragma unroll
    for (int i = 0; i < 32; i++) {
#pragma unroll
        for (int j = 0; j < 32; j++) q[j] = fmaf(p[i], sWf1[i * 32 + j], q[j]);
    }
#pragma unroll
    for (int j = 0; j < 32; j++) q[j] = q[j] > 0.f ? q[j] : SLOPE * q[j];
    float o0 = sbf2[0], o1 = sbf2[1];
#pragma unroll
    for (int i = 0; i < 32; i++) { o0 = fmaf(q[i], sWf2[i * 2], o0); o1 = fmaf(q[i], sWf2[i * 2 + 1], o1); }
    out[(size_t)nidx * 2]     = o0;
    out[(size_t)nidx * 2 + 1] = o1;
}

// ---------------- launch ------------------------------------------------------
static inline int cdiv(long long a, int b) { return (int)((a + b - 1) / b); }

extern "C" void kernel_launch(void* const* d_in, const int* in_sizes, int n_in,
                              void* d_out, int out_size)
{
    const float* x   = (const float*)d_in[0];
    const int*   ei  = (const int*)d_in[1];
    // d_in[2] edge_attr, d_in[3] We, d_in[4] be: dead code in the reference
    const float* W1l = (const float*)d_in[5];
    const float* b1  = (const float*)d_in[6];
    const float* W1r = (const float*)d_in[7];
    const float* W2l = (const float*)d_in[8];
    const float* b2  = (const float*)d_in[9];
    const float* W2r = (const float*)d_in[10];
    const float* W3l = (const float*)d_in[11];
    const float* b3  = (const float*)d_in[12];
    const float* W3r = (const float*)d_in[13];
    const float* Wp  = (const float*)d_in[14];
    const float* bp  = (const float*)d_in[15];
    const float* Wf1 = (const float*)d_in[16];
    const float* bf1 = (const float*)d_in[17];
    const float* Wf2 = (const float*)d_in[18];
    const float* bf2 = (const float*)d_in[19];

    const int n  = in_sizes[0] / 128;   // 50000
    const int ne = in_sizes[1] / 2;     // 800000
    const int* src = ei;
    const int* dst = ei + ne;

    float *cntinv, *agg, *h1, *z2, *r2, *h2, *z3, *r3, *h3;
    cudaGetSymbolAddress((void**)&cntinv, g_cntinv);
    cudaGetSymbolAddress((void**)&agg,    g_agg);
    cudaGetSymbolAddress((void**)&h1,     g_h1);
    cudaGetSymbolAddress((void**)&z2,     g_z2);
    cudaGetSymbolAddress((void**)&r2,     g_r2);
    cudaGetSymbolAddress((void**)&h2,     g_h2);
    cudaGetSymbolAddress((void**)&z3,     g_z3);
    cudaGetSymbolAddress((void**)&r3,     g_r3);
    cudaGetSymbolAddress((void**)&h3,     g_h3);
    float* out = (float*)d_out;

    const int T = 256;
    const int gM = cdiv(n, GBM);   // 391

    // prologue ordered so the ncu-captured launch (#4) is agg_kernel
    zero4_kernel<<<cdiv(n / 4, T), T>>>(cntinv, n / 4);                 // 1
    zero4_kernel<<<cdiv((long long)n * 32, T), T>>>(agg, n * 32);       // 2
    count_kernel<<<cdiv(ne, T), T>>>(dst, cntinv, ne);                  // 3
    agg_kernel<<<cdiv((long long)ne * 32, T), T>>>(x, src, dst, agg, 32, ne); // 4
    invert_kernel<<<cdiv(n, T), T>>>(cntinv, n);                        // 5

    // ---- layer 1: one K-concat GEMM: h1 = leaky([agg*cntinv | x] @ [W1l;W1r] + b1)
    gemm2_kernel<FLAG_CONCAT | FLAG_BIAS | FLAG_LEAKY><<<dim3(512 / GBN, gM), T>>>(
        agg, x, 128, cntinv, W1l, W1r, h1, nullptr, b1, n, 512, 256);   // 6

    // ---- layer 2: N-concat GEMM [z2|r2] = h1 @ [W2l|W2r]; aggregate z2 (256d)
    gemm2_kernel<FLAG_NCAT><<<dim3(512 / GBN, gM), T>>>(
        h1, nullptr, 0, nullptr, W2l, W2r, z2, r2, nullptr, n, 512, 512);
    zero4_kernel<<<cdiv((long long)n * 64, T), T>>>(agg, n * 64);
    agg_kernel<<<cdiv((long long)ne * 64, T), T>>>(z2, src, dst, agg, 64, ne);
    ew_kernel<<<cdiv((long long)n * 64, T), T>>>(agg, cntinv, r2, b2, h2, 64, n);

    // ---- layer 3: N-concat GEMM [z3|r3] = h2 @ [W3l|W3r]; aggregate z3 (64d)
    gemm2_kernel<FLAG_NCAT><<<dim3(128 / GBN, gM), T>>>(
        h2, nullptr, 0, nullptr, W3l, W3r, z3, r3, nullptr, n, 128, 256);
    zero4_kernel<<<cdiv((long long)n * 16, T), T>>>(agg, n * 16);
    agg_kernel<<<cdiv((long long)ne * 16, T), T>>>(z3, src, dst, agg, 16, ne);
    ew_kernel<<<cdiv((long long)n * 16, T), T>>>(agg, cntinv, r3, b3, h3, 16, n);

    // ---- fused head
    head_kernel<<<cdiv(n, 128), 128>>>(h3, Wp, bp, Wf1, bf1, Wf2, bf2, out, n);
}

// round 5
// speedup vs baseline: 3.0028x; 3.0028x over previous
#include <cuda_runtime.h>
#include <cstdint>

#define SLOPE 0.15f

static const int NN = 50000;
static const int NE = 800000;

// ---------------- device scratch ----------------------------------------------
__device__ int   g_deg[NN];
__device__ int   g_rowptr[NN + 1];
__device__ int   g_cursor[NN];
__device__ int   g_csr[NE];
__device__ float g_mean1[NN * 128];
__device__ float g_h1[NN * 512];
__device__ float g_z2[NN * 256];
__device__ float g_r2[NN * 256];
__device__ float g_h2[NN * 256];
__device__ float g_z3[NN * 64];
__device__ float g_r3[NN * 64];
__device__ float g_h3[NN * 64];

// ---------------- CSR build ----------------------------------------------------
__global__ void zeroi_kernel(int* __restrict__ p, int n) {
    int i = blockIdx.x * blockDim.x + threadIdx.x;
    if (i < n) p[i] = 0;
}

__global__ void counti_kernel(const int* __restrict__ dst, int* __restrict__ deg, int ne) {
    int e = blockIdx.x * blockDim.x + threadIdx.x;
    if (e < ne) atomicAdd(&deg[dst[e]], 1);
}

__global__ void scan_kernel(const int* __restrict__ deg, int* __restrict__ rowptr,
                            int* __restrict__ cursor, int n) {
    __shared__ int part[1024];
    const int t = threadIdx.x;
    const int chunk = (n + 1023) >> 10;
    int lo = t * chunk;
    int hi = lo + chunk; if (hi > n) hi = n;
    int s = 0;
    for (int i = lo; i < hi; i++) s += deg[i];
    part[t] = s;
    __syncthreads();
    for (int off = 1; off < 1024; off <<= 1) {
        int v = (t >= off) ? part[t - off] : 0;
        __syncthreads();
        part[t] += v;
        __syncthreads();
    }
    int base = (t == 0) ? 0 : part[t - 1];
    for (int i = lo; i < hi; i++) {
        rowptr[i] = base; cursor[i] = base;
        base += deg[i];
    }
    if (t == 1023) rowptr[n] = base;
}

__global__ void scatter_kernel(const int* __restrict__ src, const int* __restrict__ dst,
                               int* __restrict__ cursor, int* __restrict__ csr, int ne) {
    int e = blockIdx.x * blockDim.x + threadIdx.x;
    if (e < ne) {
        int p = atomicAdd(&cursor[dst[e]], 1);
        csr[p] = src[e];
    }
}

// ---------------- CSR mean-aggregate (optionally fused SAGE epilogue) ----------
// out[node] = mean_{s in csr row} feat[s]           (FUSE=false)
// out[node] = leaky(mean + bias + r[node])          (FUSE=true)
template<int D4, bool FUSE>
__global__ __launch_bounds__(256) void csr_agg_kernel(
    const float* __restrict__ feat,
    const int* __restrict__ rowptr, const int* __restrict__ csr,
    const float* __restrict__ r, const float* __restrict__ bias,
    float* __restrict__ out, int n)
{
    const int L = (D4 < 32) ? D4 : 32;   // lanes per node
    const int V = D4 / L;                // float4s per lane
    const int npb = 256 / L;
    int node = blockIdx.x * npb + threadIdx.x / L;
    int sl = threadIdx.x % L;
    if (node >= n) return;
    int beg = rowptr[node], end = rowptr[node + 1];
    float4 acc[V];
#pragma unroll
    for (int v = 0; v < V; v++) acc[v] = make_float4(0.f, 0.f, 0.f, 0.f);
    const float4* f4 = (const float4*)feat;
    for (int j = beg; j < end; j++) {
        int s = __ldg(&csr[j]);
#pragma unroll
        for (int v = 0; v < V; v++) {
            float4 x = f4[(size_t)s * D4 + sl + v * L];
            acc[v].x += x.x; acc[v].y += x.y; acc[v].z += x.z; acc[v].w += x.w;
        }
    }
    float inv = 1.0f / fmaxf((float)(end - beg), 1.0f);
#pragma unroll
    for (int v = 0; v < V; v++) {
        int c4 = sl + v * L;
        float4 o = make_float4(acc[v].x * inv, acc[v].y * inv, acc[v].z * inv, acc[v].w * inv);
        if (FUSE) {
            float4 rr = ((const float4*)r)[(size_t)node * D4 + c4];
            float4 bb = ((const float4*)bias)[c4];
            o.x += bb.x + rr.x; o.y += bb.y + rr.y;
            o.z += bb.z + rr.z; o.w += bb.w + rr.w;
            o.x = o.x > 0.f ? o.x : SLOPE * o.x;
            o.y = o.y > 0.f ? o.y : SLOPE * o.y;
            o.z = o.z > 0.f ? o.z : SLOPE * o.z;
            o.w = o.w > 0.f ? o.w : SLOPE * o.w;
        }
        ((float4*)out)[(size_t)node * D4 + c4] = o;
    }
}

// ---------------- TF32 tensor-core GEMM ----------------------------------------
// C[M,N] = A[M,K] @ B[K,N], tile 128x128x16, 256 threads (8 warps, 4Mx2N),
// warp tile 32x64 via mma.m16n8k8 tf32. fp32 accumulate.
#define FLAG_CONCAT 1  // A = [A1(K1) | A2], B = [B1 ; B2] row blocks
#define FLAG_NCAT   2  // B = [B1 | B2] halves of width Nh, C = [C1 | C2]
#define FLAG_BIAS   4
#define FLAG_LEAKY  8

__device__ __forceinline__ unsigned f2tf(float f) {
    unsigned r; asm("cvt.rna.tf32.f32 %0, %1;" : "=r"(r) : "f"(f)); return r;
}
__device__ __forceinline__ void mma_tf32(float* c, const unsigned* a, unsigned b0, unsigned b1) {
    asm("mma.sync.aligned.m16n8k8.row.col.f32.tf32.tf32.f32 "
        "{%0,%1,%2,%3}, {%4,%5,%6,%7}, {%8,%9}, {%0,%1,%2,%3};"
        : "+f"(c[0]), "+f"(c[1]), "+f"(c[2]), "+f"(c[3])
        : "r"(a[0]), "r"(a[1]), "r"(a[2]), "r"(a[3]), "r"(b0), "r"(b1));
}

#define ASTR 20    // 16 + 4 pad (u32 units) — conflict-free for frag reads
#define BSTR 136   // 128 + 8 pad — conflict-free (bank = 8k + c)

template<int FLAGS>
__global__ __launch_bounds__(256, 2) void gemm_tf32_kernel(
    const float* __restrict__ A1, const float* __restrict__ A2, int K1,
    const float* __restrict__ B1, const float* __restrict__ B2,
    float* __restrict__ C1, float* __restrict__ C2,
    const float* __restrict__ bias, int M, int N, int K)
{
    __shared__ unsigned As[128 * ASTR];
    __shared__ unsigned Bs[16 * BSTR];
    const int tid = threadIdx.x;
    const int bm = blockIdx.y * 128;
    const int bn = blockIdx.x * 128;
    const int Nh = N >> 1;

    const int w = tid >> 5, lane = tid & 31;
    const int wm = (w & 3) * 32;
    const int wn = (w >> 2) * 64;
    const int lr = lane >> 2, lc = lane & 3;

    // loaders: A 128x16 (2 float4/thread), B 16x128 (2 float4/thread)
    const int am0 = tid >> 2;           // 0..63 (l adds 64)
    const int ak4 = (tid & 3) * 4;
    const int bk0 = tid >> 5;           // 0..7  (l adds 8)
    const int bc  = (tid & 31) * 4;
    const int K2 = K - K1;

    float acc[2][8][4];
#pragma unroll
    for (int mi = 0; mi < 2; mi++)
#pragma unroll
        for (int ni = 0; ni < 8; ni++)
#pragma unroll
            for (int q = 0; q < 4; q++) acc[mi][ni][q] = 0.f;

    float4 avr[2], bvr[2];

    auto load_tile = [&](int k0) {
#pragma unroll
        for (int l = 0; l < 2; l++) {
            int gm = bm + am0 + 64 * l;
            int kg = k0 + ak4;
            float4 v = make_float4(0.f, 0.f, 0.f, 0.f);
            if (gm < M) {
                const float* s;
                if (FLAGS & FLAG_CONCAT)
                    s = (kg < K1) ? A1 + (size_t)gm * K1 + kg
                                  : A2 + (size_t)gm * K2 + (kg - K1);
                else
                    s = A1 + (size_t)gm * K + kg;
                v = *(const float4*)s;
            }
            avr[l] = v;
        }
#pragma unroll
        for (int l = 0; l < 2; l++) {
            int kg = k0 + bk0 + 8 * l;
            const float* s;
            if (FLAGS & FLAG_CONCAT) {
                s = (kg < K1) ? B1 + (size_t)kg * N + bn + bc
                              : B2 + (size_t)(kg - K1) * N + bn + bc;
            } else if (FLAGS & FLAG_NCAT) {
                int c = bn + bc;
                s = (c < Nh) ? B1 + (size_t)kg * Nh + c
                             : B2 + (size_t)kg * Nh + (c - Nh);
            } else {
                s = B1 + (size_t)kg * N + bn + bc;
            }
            bvr[l] = *(const float4*)s;
        }
    };
    auto store_tile = [&]() {
#pragma unroll
        for (int l = 0; l < 2; l++) {
            int m = am0 + 64 * l;
            uint4 u = make_uint4(f2tf(avr[l].x), f2tf(avr[l].y), f2tf(avr[l].z), f2tf(avr[l].w));
            *(uint4*)&As[m * ASTR + ak4] = u;
        }
#pragma unroll
        for (int l = 0; l < 2; l++) {
            int k = bk0 + 8 * l;
            uint4 u = make_uint4(f2tf(bvr[l].x), f2tf(bvr[l].y), f2tf(bvr[l].z), f2tf(bvr[l].w));
            *(uint4*)&Bs[k * BSTR + bc] = u;
        }
    };

    load_tile(0);
    store_tile();
    __syncthreads();

    const int kt = K / 16;
    for (int t = 0; t < kt; t++) {
        if (t + 1 < kt) load_tile((t + 1) * 16);
#pragma unroll
        for (int kc = 0; kc < 16; kc += 8) {
            unsigned a[2][4];
#pragma unroll
            for (int mi = 0; mi < 2; mi++) {
                int ar = wm + mi * 16 + lr;
                a[mi][0] = As[ar * ASTR + kc + lc];
                a[mi][1] = As[(ar + 8) * ASTR + kc + lc];
                a[mi][2] = As[ar * ASTR + kc + lc + 4];
                a[mi][3] = As[(ar + 8) * ASTR + kc + lc + 4];
            }
#pragma unroll
            for (int ni = 0; ni < 8; ni++) {
                unsigned b0 = Bs[(kc + lc) * BSTR + wn + ni * 8 + lr];
                unsigned b1 = Bs[(kc + lc + 4) * BSTR + wn + ni * 8 + lr];
                mma_tf32(acc[0][ni], a[0], b0, b1);
                mma_tf32(acc[1][ni], a[1], b0, b1);
            }
        }
        __syncthreads();
        if (t + 1 < kt) { store_tile(); __syncthreads(); }
    }

    // epilogue
    float* Cout = C1; int coff = 0; int cstr = N;
    if (FLAGS & FLAG_NCAT) {
        cstr = Nh;
        if (bn + wn >= Nh) { Cout = C2; coff = -Nh; }
    }
#pragma unroll
    for (int mi = 0; mi < 2; mi++) {
#pragma unroll
        for (int ni = 0; ni < 8; ni++) {
            int r0 = bm + wm + mi * 16 + lr;
            int col = bn + wn + ni * 8 + 2 * lc;
            float2 v0 = make_float2(acc[mi][ni][0], acc[mi][ni][1]);
            float2 v1 = make_float2(acc[mi][ni][2], acc[mi][ni][3]);
            if (FLAGS & FLAG_BIAS) {
                float2 bb = *(const float2*)(bias + col);
                v0.x += bb.x; v0.y += bb.y;
                v1.x += bb.x; v1.y += bb.y;
            }
            if (FLAGS & FLAG_LEAKY) {
                v0.x = v0.x > 0.f ? v0.x : SLOPE * v0.x;
                v0.y = v0.y > 0.f ? v0.y : SLOPE * v0.y;
                v1.x = v1.x > 0.f ? v1.x : SLOPE * v1.x;
                v1.y = v1.y > 0.f ? v1.y : SLOPE * v1.y;
            }
            if (r0 < M)     *(float2*)(Cout + (size_t)r0 * cstr + col + coff) = v0;
            if (r0 + 8 < M) *(float2*)(Cout + (size_t)(r0 + 8) * cstr + col + coff) = v1;
        }
    }
}

// ---------------- fused head: h3[64] -> Wp(32) -> leaky(Wf1(32)) -> Wf2(2) ----
__global__ __launch_bounds__(128) void head_kernel(
    const float* __restrict__ h3,
    const float* __restrict__ Wp, const float* __restrict__ bp,
    const float* __restrict__ Wf1, const float* __restrict__ bf1,
    const float* __restrict__ Wf2, const float* __restrict__ bf2,
    float* __restrict__ out, int n)
{
    __shared__ float sWp[64 * 32], sWf1[32 * 32], sWf2[64], sbp[32], sbf1[32], sbf2[2];
    for (int i = threadIdx.x; i < 64 * 32; i += blockDim.x) sWp[i] = Wp[i];
    for (int i = threadIdx.x; i < 32 * 32; i += blockDim.x) sWf1[i] = Wf1[i];
    for (int i = threadIdx.x; i < 64; i += blockDim.x) sWf2[i] = Wf2[i];
    if (threadIdx.x < 32) { sbp[threadIdx.x] = bp[threadIdx.x]; sbf1[threadIdx.x] = bf1[threadIdx.x]; }
    if (threadIdx.x < 2) sbf2[threadIdx.x] = bf2[threadIdx.x];
    __syncthreads();
    int nidx = blockIdx.x * blockDim.x + threadIdx.x;
    if (nidx >= n) return;

    float p[32];
#pragma unroll
    for (int j = 0; j < 32; j++) p[j] = sbp[j];
    const float* hx = h3 + (size_t)nidx * 64;
    for (int i = 0; i < 64; i++) {
        float xi = hx[i];
#pragma unroll
        for (int j = 0; j < 32; j++) p[j] = fmaf(xi, sWp[i * 32 + j], p[j]);
    }
    float q[32];
#pragma unroll
    for (int j = 0; j < 32; j++) q[j] = sbf1[j];
#pragma unroll
    for (int i = 0; i < 32; i++) {
#pragma unroll
        for (int j = 0; j < 32; j++) q[j] = fmaf(p[i], sWf1[i * 32 + j], q[j]);
    }
#pragma unroll
    for (int j = 0; j < 32; j++) q[j] = q[j] > 0.f ? q[j] : SLOPE * q[j];
    float o0 = sbf2[0], o1 = sbf2[1];
#pragma unroll
    for (int i = 0; i < 32; i++) { o0 = fmaf(q[i], sWf2[i * 2], o0); o1 = fmaf(q[i], sWf2[i * 2 + 1], o1); }
    out[(size_t)nidx * 2]     = o0;
    out[(size_t)nidx * 2 + 1] = o1;
}

// ---------------- launch ------------------------------------------------------
static inline int cdiv(long long a, int b) { return (int)((a + b - 1) / b); }

extern "C" void kernel_launch(void* const* d_in, const int* in_sizes, int n_in,
                              void* d_out, int out_size)
{
    const float* x   = (const float*)d_in[0];
    const int*   ei  = (const int*)d_in[1];
    // d_in[2..4] edge_attr/We/be: dead code in the reference
    const float* W1l = (const float*)d_in[5];
    const float* b1  = (const float*)d_in[6];
    const float* W1r = (const float*)d_in[7];
    const float* W2l = (const float*)d_in[8];
    const float* b2  = (const float*)d_in[9];
    const float* W2r = (const float*)d_in[10];
    const float* W3l = (const float*)d_in[11];
    const float* b3  = (const float*)d_in[12];
    const float* W3r = (const float*)d_in[13];
    const float* Wp  = (const float*)d_in[14];
    const float* bp  = (const float*)d_in[15];
    const float* Wf1 = (const float*)d_in[16];
    const float* bf1 = (const float*)d_in[17];
    const float* Wf2 = (const float*)d_in[18];
    const float* bf2 = (const float*)d_in[19];

    const int n  = in_sizes[0] / 128;   // 50000
    const int ne = in_sizes[1] / 2;     // 800000
    const int* src = ei;
    const int* dst = ei + ne;

    int *deg, *rowptr, *cursor, *csr;
    float *mean1, *h1, *z2, *r2, *h2, *z3, *r3, *h3;
    cudaGetSymbolAddress((void**)&deg,    g_deg);
    cudaGetSymbolAddress((void**)&rowptr, g_rowptr);
    cudaGetSymbolAddress((void**)&cursor, g_cursor);
    cudaGetSymbolAddress((void**)&csr,    g_csr);
    cudaGetSymbolAddress((void**)&mean1,  g_mean1);
    cudaGetSymbolAddress((void**)&h1,     g_h1);
    cudaGetSymbolAddress((void**)&z2,     g_z2);
    cudaGetSymbolAddress((void**)&r2,     g_r2);
    cudaGetSymbolAddress((void**)&h2,     g_h2);
    cudaGetSymbolAddress((void**)&z3,     g_z3);
    cudaGetSymbolAddress((void**)&r3,     g_r3);
    cudaGetSymbolAddress((void**)&h3,     g_h3);
    float* out = (float*)d_out;

    const int T = 256;
    const int gM = cdiv(n, 128);   // 391

    // ---- CSR build
    zeroi_kernel<<<cdiv(n, T), T>>>(deg, n);                            // 1
    counti_kernel<<<cdiv(ne, T), T>>>(dst, deg, ne);                    // 2
    scan_kernel<<<1, 1024>>>(deg, rowptr, cursor, n);                   // 3
    scatter_kernel<<<cdiv(ne, T), T>>>(src, dst, cursor, csr, ne);      // 4

    // ---- layer 1: mean1 = mean_csr(x); h1 = leaky([mean1|x] @ [W1l;W1r] + b1)
    csr_agg_kernel<32, false><<<cdiv(n, 8), T>>>(x, rowptr, csr, nullptr, nullptr, mean1, n); // 5
    gemm_tf32_kernel<FLAG_CONCAT | FLAG_BIAS | FLAG_LEAKY><<<dim3(4, gM), T>>>(
        mean1, x, 128, W1l, W1r, h1, nullptr, b1, n, 512, 256);         // 6 (profiled)

    // ---- layer 2: [z2|r2] = h1 @ [W2l|W2r]; h2 = leaky(mean_csr(z2) + b2 + r2)
    gemm_tf32_kernel<FLAG_NCAT><<<dim3(4, gM), T>>>(
        h1, nullptr, 0, W2l, W2r, z2, r2, nullptr, n, 512, 512);
    csr_agg_kernel<64, true><<<cdiv(n, 8), T>>>(z2, rowptr, csr, r2, b2, h2, n);

    // ---- layer 3: [z3|r3] = h2 @ [W3l|W3r] (N = 64+64 = 128!); fuse epilogue
    gemm_tf32_kernel<FLAG_NCAT><<<dim3(1, gM), T>>>(
        h2, nullptr, 0, W3l, W3r, z3, r3, nullptr, n, 128, 256);
    csr_agg_kernel<16, true><<<cdiv(n, 16), T>>>(z3, rowptr, csr, r3, b3, h3, n);

    // ---- fused head
    head_kernel<<<cdiv(n, 128), 128>>>(h3, Wp, bp, Wf1, bf1, Wf2, bf2, out, n);
}

// round 6
// speedup vs baseline: 3.2768x; 1.0912x over previous
#include <cuda_runtime.h>
#include <cstdint>

#define SLOPE 0.15f

static const int NN = 50000;
static const int NE = 800000;

// ---------------- device scratch ----------------------------------------------
__device__ int   g_deg[NN];
__device__ int   g_rowptr[NN + 1];
__device__ int   g_cursor[NN];
__device__ int   g_csr[NE];
__device__ float g_mean1[NN * 128];
__device__ float g_h1[NN * 512];
__device__ float g_z2[NN * 256];
__device__ float g_r2[NN * 256];
__device__ float g_h2[NN * 256];
__device__ float g_z3[NN * 64];
__device__ float g_r3[NN * 64];
__device__ float g_h3[NN * 64];

// ---------------- CSR build ----------------------------------------------------
__global__ void counti_kernel(const int* __restrict__ dst, int* __restrict__ deg, int ne) {
    int e = blockIdx.x * blockDim.x + threadIdx.x;
    if (e < ne) atomicAdd(&deg[dst[e]], 1);
}

__global__ void scan_kernel(const int* __restrict__ deg, int* __restrict__ rowptr,
                            int* __restrict__ cursor, int n) {
    __shared__ int part[1024];
    const int t = threadIdx.x;
    const int chunk = (n + 1023) >> 10;
    int lo = t * chunk;
    int hi = lo + chunk; if (hi > n) hi = n;
    int s = 0;
    for (int i = lo; i < hi; i++) s += deg[i];
    part[t] = s;
    __syncthreads();
    for (int off = 1; off < 1024; off <<= 1) {
        int v = (t >= off) ? part[t - off] : 0;
        __syncthreads();
        part[t] += v;
        __syncthreads();
    }
    int base = (t == 0) ? 0 : part[t - 1];
    for (int i = lo; i < hi; i++) {
        rowptr[i] = base; cursor[i] = base;
        base += deg[i];
    }
    if (t == 1023) rowptr[n] = base;
}

__global__ void scatter_kernel(const int* __restrict__ src, const int* __restrict__ dst,
                               int* __restrict__ cursor, int* __restrict__ csr, int ne) {
    int e = blockIdx.x * blockDim.x + threadIdx.x;
    if (e < ne) {
        int p = atomicAdd(&cursor[dst[e]], 1);
        csr[p] = src[e];
    }
}

// ---------------- CSR mean-aggregate (optionally fused SAGE epilogue) ----------
template<int D4, bool FUSE>
__global__ __launch_bounds__(256) void csr_agg_kernel(
    const float* __restrict__ feat,
    const int* __restrict__ rowptr, const int* __restrict__ csr,
    const float* __restrict__ r, const float* __restrict__ bias,
    float* __restrict__ out, int n)
{
    const int L = (D4 < 32) ? D4 : 32;   // lanes per node
    const int V = D4 / L;                // float4s per lane
    const int npb = 256 / L;
    int node = blockIdx.x * npb + threadIdx.x / L;
    int sl = threadIdx.x % L;
    if (node >= n) return;
    int beg = rowptr[node], end = rowptr[node + 1];
    float4 acc[V];
#pragma unroll
    for (int v = 0; v < V; v++) acc[v] = make_float4(0.f, 0.f, 0.f, 0.f);
    const float4* f4 = (const float4*)feat;
    for (int j = beg; j < end; j++) {
        int s = __ldg(&csr[j]);
#pragma unroll
        for (int v = 0; v < V; v++) {
            float4 x = f4[(size_t)s * D4 + sl + v * L];
            acc[v].x += x.x; acc[v].y += x.y; acc[v].z += x.z; acc[v].w += x.w;
        }
    }
    float inv = 1.0f / fmaxf((float)(end - beg), 1.0f);
#pragma unroll
    for (int v = 0; v < V; v++) {
        int c4 = sl + v * L;
        float4 o = make_float4(acc[v].x * inv, acc[v].y * inv, acc[v].z * inv, acc[v].w * inv);
        if (FUSE) {
            float4 rr = ((const float4*)r)[(size_t)node * D4 + c4];
            float4 bb = ((const float4*)bias)[c4];
            o.x += bb.x + rr.x; o.y += bb.y + rr.y;
            o.z += bb.z + rr.z; o.w += bb.w + rr.w;
            o.x = o.x > 0.f ? o.x : SLOPE * o.x;
            o.y = o.y > 0.f ? o.y : SLOPE * o.y;
            o.z = o.z > 0.f ? o.z : SLOPE * o.z;
            o.w = o.w > 0.f ? o.w : SLOPE * o.w;
        }
        ((float4*)out)[(size_t)node * D4 + c4] = o;
    }
}

// ---------------- TF32 tensor-core GEMM, cp.async double-buffered --------------
// C[M,N] = A[M,K] @ B[K,N], tile 128x128x16, 256 threads (8 warps, 4Mx2N),
// warp tile 32x64 via mma.m16n8k8 tf32, fp32 accumulate. Tiles are copied
// global->smem with cp.async as raw fp32; mma reads them as tf32 (the HW
// ignores the low 13 mantissa bits => rz rounding instead of rna).
#define FLAG_CONCAT 1  // A = [A1(K1) | A2], B = [B1 ; B2] row blocks
#define FLAG_NCAT   2  // B = [B1 | B2] halves of width Nh, C = [C1 | C2]
#define FLAG_BIAS   4
#define FLAG_LEAKY  8

__device__ __forceinline__ void mma_tf32(float* c, const unsigned* a, unsigned b0, unsigned b1) {
    asm("mma.sync.aligned.m16n8k8.row.col.f32.tf32.tf32.f32 "
        "{%0,%1,%2,%3}, {%4,%5,%6,%7}, {%8,%9}, {%0,%1,%2,%3};"
        : "+f"(c[0]), "+f"(c[1]), "+f"(c[2]), "+f"(c[3])
        : "r"(a[0]), "r"(a[1]), "r"(a[2]), "r"(a[3]), "r"(b0), "r"(b1));
}

__device__ __forceinline__ void cp16(unsigned saddr, const void* g, bool ok) {
    int sz = ok ? 16 : 0;
    asm volatile("cp.async.ca.shared.global [%0], [%1], 16, %2;"
                 :: "r"(saddr), "l"(g), "r"(sz));
}
#define CP_COMMIT() asm volatile("cp.async.commit_group;")
#define CP_WAIT1()  asm volatile("cp.async.wait_group 1;")
#define CP_WAIT0()  asm volatile("cp.async.wait_group 0;")

#define ASTR 20    // 16 + 4 pad (u32 units)
#define BSTR 136   // 128 + 8 pad

template<int FLAGS>
__global__ __launch_bounds__(256, 2) void gemm_tf32_kernel(
    const float* __restrict__ A1, const float* __restrict__ A2, int K1,
    const float* __restrict__ B1, const float* __restrict__ B2,
    float* __restrict__ C1, float* __restrict__ C2,
    const float* __restrict__ bias, int M, int N, int K)
{
    __shared__ unsigned As[2][128 * ASTR];
    __shared__ unsigned Bs[2][16 * BSTR];
    const int tid = threadIdx.x;
    const int bm = blockIdx.y * 128;
    const int bn = blockIdx.x * 128;
    const int Nh = N >> 1;

    const int w = tid >> 5, lane = tid & 31;
    const int wm = (w & 3) * 32;
    const int wn = (w >> 2) * 64;
    const int lr = lane >> 2, lc = lane & 3;

    // loaders: A 128x16 (2 x 16B/thread), B 16x128 (2 x 16B/thread)
    const int am0 = tid >> 2;           // 0..63 (l adds 64)
    const int ak4 = (tid & 3) * 4;
    const int bk0 = tid >> 5;           // 0..7  (l adds 8)
    const int bc  = (tid & 31) * 4;
    const int K2 = K - K1;

    bool aok[2];
    unsigned adst[2], bdst[2];
#pragma unroll
    for (int l = 0; l < 2; l++) {
        aok[l]  = (bm + am0 + 64 * l) < M;
        adst[l] = (unsigned)__cvta_generic_to_shared(&As[0][(am0 + 64 * l) * ASTR + ak4]);
        bdst[l] = (unsigned)__cvta_generic_to_shared(&Bs[0][(bk0 + 8 * l) * BSTR + bc]);
    }
    const unsigned aStage = sizeof(unsigned) * 128 * ASTR;
    const unsigned bStage = sizeof(unsigned) * 16 * BSTR;

    auto issue = [&](int stage, int k0) {
#pragma unroll
        for (int l = 0; l < 2; l++) {
            int gm = bm + am0 + 64 * l;
            int kg = k0 + ak4;
            const float* s;
            if (FLAGS & FLAG_CONCAT)
                s = (kg < K1) ? A1 + (size_t)gm * K1 + kg
                              : A2 + (size_t)gm * K2 + (kg - K1);
            else
                s = A1 + (size_t)gm * K + kg;
            cp16(adst[l] + stage * aStage, s, aok[l]);
        }
#pragma unroll
        for (int l = 0; l < 2; l++) {
            int kg = k0 + bk0 + 8 * l;
            const float* s;
            if (FLAGS & FLAG_CONCAT) {
                s = (kg < K1) ? B1 + (size_t)kg * N + bn + bc
                              : B2 + (size_t)(kg - K1) * N + bn + bc;
            } else if (FLAGS & FLAG_NCAT) {
                int c = bn + bc;
                s = (c < Nh) ? B1 + (size_t)kg * Nh + c
                             : B2 + (size_t)kg * Nh + (c - Nh);
            } else {
                s = B1 + (size_t)kg * N + bn + bc;
            }
            cp16(bdst[l] + stage * bStage, s, true);
        }
    };

    float acc[2][8][4];
#pragma unroll
    for (int mi = 0; mi < 2; mi++)
#pragma unroll
        for (int ni = 0; ni < 8; ni++)
#pragma unroll
            for (int q = 0; q < 4; q++) acc[mi][ni][q] = 0.f;

    issue(0, 0);
    CP_COMMIT();

    const int kt = K / 16;
    for (int t = 0; t < kt; t++) {
        if (t + 1 < kt) {
            issue((t + 1) & 1, (t + 1) * 16);
            CP_COMMIT();
            CP_WAIT1();
        } else {
            CP_WAIT0();
        }
        __syncthreads();
        const unsigned* Ab = As[t & 1];
        const unsigned* Bb = Bs[t & 1];
#pragma unroll
        for (int kc = 0; kc < 16; kc += 8) {
            unsigned a[2][4];
#pragma unroll
            for (int mi = 0; mi < 2; mi++) {
                int ar = wm + mi * 16 + lr;
                a[mi][0] = Ab[ar * ASTR + kc + lc];
                a[mi][1] = Ab[(ar + 8) * ASTR + kc + lc];
                a[mi][2] = Ab[ar * ASTR + kc + lc + 4];
                a[mi][3] = Ab[(ar + 8) * ASTR + kc + lc + 4];
            }
#pragma unroll
            for (int ni = 0; ni < 8; ni++) {
                unsigned b0 = Bb[(kc + lc) * BSTR + wn + ni * 8 + lr];
                unsigned b1 = Bb[(kc + lc + 4) * BSTR + wn + ni * 8 + lr];
                mma_tf32(acc[0][ni], a[0], b0, b1);
                mma_tf32(acc[1][ni], a[1], b0, b1);
            }
        }
        __syncthreads();
    }

    // epilogue
    float* Cout = C1; int coff = 0; int cstr = N;
    if (FLAGS & FLAG_NCAT) {
        cstr = Nh;
        if (bn + wn >= Nh) { Cout = C2; coff = -Nh; }
    }
#pragma unroll
    for (int mi = 0; mi < 2; mi++) {
#pragma unroll
        for (int ni = 0; ni < 8; ni++) {
            int r0 = bm + wm + mi * 16 + lr;
            int col = bn + wn + ni * 8 + 2 * lc;
            float2 v0 = make_float2(acc[mi][ni][0], acc[mi][ni][1]);
            float2 v1 = make_float2(acc[mi][ni][2], acc[mi][ni][3]);
            if (FLAGS & FLAG_BIAS) {
                float2 bb = *(const float2*)(bias + col);
                v0.x += bb.x; v0.y += bb.y;
                v1.x += bb.x; v1.y += bb.y;
            }
            if (FLAGS & FLAG_LEAKY) {
                v0.x = v0.x > 0.f ? v0.x : SLOPE * v0.x;
                v0.y = v0.y > 0.f ? v0.y : SLOPE * v0.y;
                v1.x = v1.x > 0.f ? v1.x : SLOPE * v1.x;
                v1.y = v1.y > 0.f ? v1.y : SLOPE * v1.y;
            }
            if (r0 < M)     *(float2*)(Cout + (size_t)r0 * cstr + col + coff) = v0;
            if (r0 + 8 < M) *(float2*)(Cout + (size_t)(r0 + 8) * cstr + col + coff) = v1;
        }
    }
}

// ---------------- fused head: h3[64] -> Wp(32) -> leaky(Wf1(32)) -> Wf2(2) ----
__global__ __launch_bounds__(128) void head_kernel(
    const float* __restrict__ h3,
    const float* __restrict__ Wp, const float* __restrict__ bp,
    const float* __restrict__ Wf1, const float* __restrict__ bf1,
    const float* __restrict__ Wf2, const float* __restrict__ bf2,
    float* __restrict__ out, int n)
{
    __shared__ float sWp[64 * 32], sWf1[32 * 32], sWf2[64], sbp[32], sbf1[32], sbf2[2];
    for (int i = threadIdx.x; i < 64 * 32; i += blockDim.x) sWp[i] = Wp[i];
    for (int i = threadIdx.x; i < 32 * 32; i += blockDim.x) sWf1[i] = Wf1[i];
    for (int i = threadIdx.x; i < 64; i += blockDim.x) sWf2[i] = Wf2[i];
    if (threadIdx.x < 32) { sbp[threadIdx.x] = bp[threadIdx.x]; sbf1[threadIdx.x] = bf1[threadIdx.x]; }
    if (threadIdx.x < 2) sbf2[threadIdx.x] = bf2[threadIdx.x];
    __syncthreads();
    int nidx = blockIdx.x * blockDim.x + threadIdx.x;
    if (nidx >= n) return;

    float p[32];
#pragma unroll
    for (int j = 0; j < 32; j++) p[j] = sbp[j];
    const float* hx = h3 + (size_t)nidx * 64;
    for (int i = 0; i < 64; i++) {
        float xi = hx[i];
#pragma unroll
        for (int j = 0; j < 32; j++) p[j] = fmaf(xi, sWp[i * 32 + j], p[j]);
    }
    float q[32];
#pragma unroll
    for (int j = 0; j < 32; j++) q[j] = sbf1[j];
#pragma unroll
    for (int i = 0; i < 32; i++) {
#pragma unroll
        for (int j = 0; j < 32; j++) q[j] = fmaf(p[i], sWf1[i * 32 + j], q[j]);
    }
#pragma unroll
    for (int j = 0; j < 32; j++) q[j] = q[j] > 0.f ? q[j] : SLOPE * q[j];
    float o0 = sbf2[0], o1 = sbf2[1];
#pragma unroll
    for (int i = 0; i < 32; i++) { o0 = fmaf(q[i], sWf2[i * 2], o0); o1 = fmaf(q[i], sWf2[i * 2 + 1], o1); }
    out[(size_t)nidx * 2]     = o0;
    out[(size_t)nidx * 2 + 1] = o1;
}

// ---------------- launch ------------------------------------------------------
static inline int cdiv(long long a, int b) { return (int)((a + b - 1) / b); }

extern "C" void kernel_launch(void* const* d_in, const int* in_sizes, int n_in,
                              void* d_out, int out_size)
{
    const float* x   = (const float*)d_in[0];
    const int*   ei  = (const int*)d_in[1];
    // d_in[2..4] edge_attr/We/be: dead code in the reference
    const float* W1l = (const float*)d_in[5];
    const float* b1  = (const float*)d_in[6];
    const float* W1r = (const float*)d_in[7];
    const float* W2l = (const float*)d_in[8];
    const float* b2  = (const float*)d_in[9];
    const float* W2r = (const float*)d_in[10];
    const float* W3l = (const float*)d_in[11];
    const float* b3  = (const float*)d_in[12];
    const float* W3r = (const float*)d_in[13];
    const float* Wp  = (const float*)d_in[14];
    const float* bp  = (const float*)d_in[15];
    const float* Wf1 = (const float*)d_in[16];
    const float* bf1 = (const float*)d_in[17];
    const float* Wf2 = (const float*)d_in[18];
    const float* bf2 = (const float*)d_in[19];

    const int n  = in_sizes[0] / 128;   // 50000
    const int ne = in_sizes[1] / 2;     // 800000
    const int* src = ei;
    const int* dst = ei + ne;

    int *deg, *rowptr, *cursor, *csr;
    float *mean1, *h1, *z2, *r2, *h2, *z3, *r3, *h3;
    cudaGetSymbolAddress((void**)&deg,    g_deg);
    cudaGetSymbolAddress((void**)&rowptr, g_rowptr);
    cudaGetSymbolAddress((void**)&cursor, g_cursor);
    cudaGetSymbolAddress((void**)&csr,    g_csr);
    cudaGetSymbolAddress((void**)&mean1,  g_mean1);
    cudaGetSymbolAddress((void**)&h1,     g_h1);
    cudaGetSymbolAddress((void**)&z2,     g_z2);
    cudaGetSymbolAddress((void**)&r2,     g_r2);
    cudaGetSymbolAddress((void**)&h2,     g_h2);
    cudaGetSymbolAddress((void**)&z3,     g_z3);
    cudaGetSymbolAddress((void**)&r3,     g_r3);
    cudaGetSymbolAddress((void**)&h3,     g_h3);
    float* out = (float*)d_out;

    const int T = 256;
    const int gM = cdiv(n, 128);   // 391

    // ---- CSR build
    cudaMemsetAsync(deg, 0, (size_t)n * sizeof(int));
    counti_kernel<<<cdiv(ne, T), T>>>(dst, deg, ne);
    scan_kernel<<<1, 1024>>>(deg, rowptr, cursor, n);
    scatter_kernel<<<cdiv(ne, T), T>>>(src, dst, cursor, csr, ne);

    // ---- layer 1: mean1 = mean_csr(x); h1 = leaky([mean1|x] @ [W1l;W1r] + b1)
    csr_agg_kernel<32, false><<<cdiv(n, 8), T>>>(x, rowptr, csr, nullptr, nullptr, mean1, n);
    gemm_tf32_kernel<FLAG_CONCAT | FLAG_BIAS | FLAG_LEAKY><<<dim3(4, gM), T>>>(
        mean1, x, 128, W1l, W1r, h1, nullptr, b1, n, 512, 256);

    // ---- layer 2: [z2|r2] = h1 @ [W2l|W2r]; h2 = leaky(mean_csr(z2) + b2 + r2)
    gemm_tf32_kernel<FLAG_NCAT><<<dim3(4, gM), T>>>(
        h1, nullptr, 0, W2l, W2r, z2, r2, nullptr, n, 512, 512);
    csr_agg_kernel<64, true><<<cdiv(n, 8), T>>>(z2, rowptr, csr, r2, b2, h2, n);

    // ---- layer 3: [z3|r3] = h2 @ [W3l|W3r] (N = 64+64 = 128)
    gemm_tf32_kernel<FLAG_NCAT><<<dim3(1, gM), T>>>(
        h2, nullptr, 0, W3l, W3r, z3, r3, nullptr, n, 128, 256);
    csr_agg_kernel<16, true><<<cdiv(n, 16), T>>>(z3, rowptr, csr, r3, b3, h3, n);

    // ---- fused head
    head_kernel<<<cdiv(n, 128), 128>>>(h3, Wp, bp, Wf1, bf1, Wf2, bf2, out, n);
}

// round 8
// speedup vs baseline: 4.0451x; 1.2345x over previous
#include <cuda_runtime.h>
#include <cuda_fp16.h>
#include <cstdint>

#define SLOPE 0.15f

static const int NN = 50000;
static const int NE = 800000;

// ---------------- device scratch ----------------------------------------------
__device__ int    g_deg[NN];
__device__ int    g_rowptr[NN + 1];
__device__ int    g_cursor[NN];
__device__ int    g_csr[NE];
__device__ __half g_wt2h[512 * 512];          // [n][k] half, [W2l|W2r]^T
__device__ __half g_wt3h[128 * 256];          // [n][k] half, [W3l|W3r]^T
__device__ float  g_mean1[NN * 128];
__device__ __half g_h1h[(size_t)NN * 512];
__device__ float  g_c2[(size_t)NN * 512];     // [z2 | r2] fp32
__device__ __half g_h2h[NN * 256];
__device__ float  g_c3[NN * 128];             // [z3 | r3] fp32
__device__ float  g_h3[NN * 64];

__device__ __forceinline__ unsigned sm32(const void* p) {
    return (unsigned)__cvta_generic_to_shared(p);
}

// ---------------- CSR build ----------------------------------------------------
__global__ void counti_kernel(const int* __restrict__ dst, int* __restrict__ deg, int ne) {
    int e = blockIdx.x * blockDim.x + threadIdx.x;
    if (e < ne) atomicAdd(&deg[dst[e]], 1);
}

__global__ void scan_kernel(const int* __restrict__ deg, int* __restrict__ rowptr,
                            int* __restrict__ cursor, int n) {
    __shared__ int part[1024];
    const int t = threadIdx.x;
    const int chunk = (n + 1023) >> 10;
    int lo = t * chunk;
    int hi = lo + chunk; if (hi > n) hi = n;
    int s = 0;
    for (int i = lo; i < hi; i++) s += deg[i];
    part[t] = s;
    __syncthreads();
    for (int off = 1; off < 1024; off <<= 1) {
        int v = (t >= off) ? part[t - off] : 0;
        __syncthreads();
        part[t] += v;
        __syncthreads();
    }
    int base = (t == 0) ? 0 : part[t - 1];
    for (int i = lo; i < hi; i++) {
        rowptr[i] = base; cursor[i] = base;
        base += deg[i];
    }
    if (t == 1023) rowptr[n] = base;
}

__global__ void scatter_kernel(const int* __restrict__ src, const int* __restrict__ dst,
                               int* __restrict__ cursor, int* __restrict__ csr, int ne) {
    int e = blockIdx.x * blockDim.x + threadIdx.x;
    if (e < ne) {
        int p = atomicAdd(&cursor[dst[e]], 1);
        csr[p] = src[e];
    }
}

// ---------------- weight prep: transpose to [n][k] + half ----------------------
__global__ void prep_w(const float* __restrict__ W2l, const float* __restrict__ W2r,
                       const float* __restrict__ W3l, const float* __restrict__ W3r) {
    int i = blockIdx.x * blockDim.x + threadIdx.x;
    if (i < 512 * 512) {
        int nn = i >> 9, k = i & 511;
        float v = (nn < 256) ? W2l[k * 256 + nn] : W2r[k * 256 + (nn - 256)];
        g_wt2h[i] = __float2half_rn(v);
        return;
    }
    int j = i - 512 * 512;
    if (j < 128 * 256) {
        int nn = j >> 8, k = j & 255;
        float v = (nn < 64) ? W3l[k * 64 + nn] : W3r[k * 64 + (nn - 64)];
        g_wt3h[j] = __float2half_rn(v);
    }
}

// ---------------- CSR mean-aggregate (unroll-4, strided, fused epilogue) -------
// OUTH: write output as half (for feeding fp16 GEMM A operand)
template<int D4, bool FUSE, bool OUTH>
__global__ __launch_bounds__(256) void csr_agg(
    const float* __restrict__ feat, int fstr4,
    const int* __restrict__ rowptr, const int* __restrict__ csr,
    const float* __restrict__ r, int rstr4,
    const float* __restrict__ bias,
    void* __restrict__ outv, int ostr4, int n)
{
    const int L = (D4 < 32) ? D4 : 32;
    const int V = D4 / L;
    const int npb = 256 / L;
    int node = blockIdx.x * npb + threadIdx.x / L;
    int sl = threadIdx.x % L;
    if (node >= n) return;
    int beg = rowptr[node], end = rowptr[node + 1];
    const float4* f4 = (const float4*)feat;
    float4 acc[V];
#pragma unroll
    for (int v = 0; v < V; v++) acc[v] = make_float4(0.f, 0.f, 0.f, 0.f);
    int j = beg;
    for (; j + 4 <= end; j += 4) {
        int s0 = __ldg(&csr[j]),     s1 = __ldg(&csr[j + 1]);
        int s2 = __ldg(&csr[j + 2]), s3 = __ldg(&csr[j + 3]);
#pragma unroll
        for (int v = 0; v < V; v++) {
            float4 x0 = f4[(size_t)s0 * fstr4 + sl + v * L];
            float4 x1 = f4[(size_t)s1 * fstr4 + sl + v * L];
            float4 x2 = f4[(size_t)s2 * fstr4 + sl + v * L];
            float4 x3 = f4[(size_t)s3 * fstr4 + sl + v * L];
            acc[v].x += (x0.x + x1.x) + (x2.x + x3.x);
            acc[v].y += (x0.y + x1.y) + (x2.y + x3.y);
            acc[v].z += (x0.z + x1.z) + (x2.z + x3.z);
            acc[v].w += (x0.w + x1.w) + (x2.w + x3.w);
        }
    }
    for (; j < end; j++) {
        int s = __ldg(&csr[j]);
#pragma unroll
        for (int v = 0; v < V; v++) {
            float4 x = f4[(size_t)s * fstr4 + sl + v * L];
            acc[v].x += x.x; acc[v].y += x.y; acc[v].z += x.z; acc[v].w += x.w;
        }
    }
    float inv = 1.0f / fmaxf((float)(end - beg), 1.0f);
#pragma unroll
    for (int v = 0; v < V; v++) {
        int c4 = sl + v * L;
        float4 o = make_float4(acc[v].x * inv, acc[v].y * inv, acc[v].z * inv, acc[v].w * inv);
        if (FUSE) {
            float4 rr = ((const float4*)r)[(size_t)node * rstr4 + c4];
            float4 bb = ((const float4*)bias)[c4];
            o.x += bb.x + rr.x; o.y += bb.y + rr.y;
            o.z += bb.z + rr.z; o.w += bb.w + rr.w;
            o.x = o.x > 0.f ? o.x : SLOPE * o.x;
            o.y = o.y > 0.f ? o.y : SLOPE * o.y;
            o.z = o.z > 0.f ? o.z : SLOPE * o.z;
            o.w = o.w > 0.f ? o.w : SLOPE * o.w;
        }
        if (OUTH) {
            __half2 p0 = __float22half2_rn(make_float2(o.x, o.y));
            __half2 p1 = __float22half2_rn(make_float2(o.z, o.w));
            __half2* dst = (__half2*)((__half*)outv + ((size_t)node * ostr4 + c4) * 4);
            dst[0] = p0; dst[1] = p1;
        } else {
            ((float4*)outv)[(size_t)node * ostr4 + c4] = o;
        }
    }
}

// ---------------- TF32 tensor-core GEMM (layer 1), cp.async double-buffered ----
// C = [A1|A2] @ [B1;B2] + bias, leaky; optional half output.
__device__ __forceinline__ void mma_tf32(float* c, const unsigned* a, unsigned b0, unsigned b1) {
    asm("mma.sync.aligned.m16n8k8.row.col.f32.tf32.tf32.f32 "
        "{%0,%1,%2,%3}, {%4,%5,%6,%7}, {%8,%9}, {%0,%1,%2,%3};"
        : "+f"(c[0]), "+f"(c[1]), "+f"(c[2]), "+f"(c[3])
        : "r"(a[0]), "r"(a[1]), "r"(a[2]), "r"(a[3]), "r"(b0), "r"(b1));
}
__device__ __forceinline__ void cp16(unsigned saddr, const void* g, bool ok) {
    int sz = ok ? 16 : 0;
    asm volatile("cp.async.cg.shared.global [%0], [%1], 16, %2;"
                 :: "r"(saddr), "l"(g), "r"(sz));
}
#define CP_COMMIT() asm volatile("cp.async.commit_group;")
#define CP_WAIT1()  asm volatile("cp.async.wait_group 1;")
#define CP_WAIT0()  asm volatile("cp.async.wait_group 0;")

#define ASTR 20
#define BSTR 136

template<bool HOUT>
__global__ __launch_bounds__(256, 2) void gemm_tf32_l1(
    const float* __restrict__ A1, const float* __restrict__ A2, int K1,
    const float* __restrict__ B1, const float* __restrict__ B2,
    void* __restrict__ Cv, const float* __restrict__ bias,
    int M, int N, int K)
{
    __shared__ unsigned As[2][128 * ASTR];
    __shared__ unsigned Bs[2][16 * BSTR];
    const int tid = threadIdx.x;
    const int bm = blockIdx.y * 128;
    const int bn = blockIdx.x * 128;

    const int w = tid >> 5, lane = tid & 31;
    const int wm = (w & 3) * 32;
    const int wn = (w >> 2) * 64;
    const int lr = lane >> 2, lc = lane & 3;

    const int am0 = tid >> 2;
    const int ak4 = (tid & 3) * 4;
    const int bk0 = tid >> 5;
    const int bc  = (tid & 31) * 4;
    const int K2 = K - K1;

    bool aok[2];
    unsigned adst[2], bdst[2];
#pragma unroll
    for (int l = 0; l < 2; l++) {
        aok[l]  = (bm + am0 + 64 * l) < M;
        adst[l] = sm32(&As[0][(am0 + 64 * l) * ASTR + ak4]);
        bdst[l] = sm32(&Bs[0][(bk0 + 8 * l) * BSTR + bc]);
    }
    const unsigned aStage = sizeof(unsigned) * 128 * ASTR;
    const unsigned bStage = sizeof(unsigned) * 16 * BSTR;

    auto issue = [&](int stage, int k0) {
#pragma unroll
        for (int l = 0; l < 2; l++) {
            int gm = bm + am0 + 64 * l;
            int kg = k0 + ak4;
            const float* s = (kg < K1) ? A1 + (size_t)gm * K1 + kg
                                       : A2 + (size_t)gm * K2 + (kg - K1);
            cp16(adst[l] + stage * aStage, s, aok[l]);
        }
#pragma unroll
        for (int l = 0; l < 2; l++) {
            int kg = k0 + bk0 + 8 * l;
            const float* s = (kg < K1) ? B1 + (size_t)kg * N + bn + bc
                                       : B2 + (size_t)(kg - K1) * N + bn + bc;
            cp16(bdst[l] + stage * bStage, s, true);
        }
    };

    float acc[2][8][4];
#pragma unroll
    for (int mi = 0; mi < 2; mi++)
#pragma unroll
        for (int ni = 0; ni < 8; ni++)
#pragma unroll
            for (int q = 0; q < 4; q++) acc[mi][ni][q] = 0.f;

    issue(0, 0);
    CP_COMMIT();

    const int kt = K / 16;
    for (int t = 0; t < kt; t++) {
        if (t + 1 < kt) {
            issue((t + 1) & 1, (t + 1) * 16);
            CP_COMMIT();
            CP_WAIT1();
        } else {
            CP_WAIT0();
        }
        __syncthreads();
        const unsigned* Ab = As[t & 1];
        const unsigned* Bb = Bs[t & 1];
#pragma unroll
        for (int kc = 0; kc < 16; kc += 8) {
            unsigned a[2][4];
#pragma unroll
            for (int mi = 0; mi < 2; mi++) {
                int ar = wm + mi * 16 + lr;
                a[mi][0] = Ab[ar * ASTR + kc + lc];
                a[mi][1] = Ab[(ar + 8) * ASTR + kc + lc];
                a[mi][2] = Ab[ar * ASTR + kc + lc + 4];
                a[mi][3] = Ab[(ar + 8) * ASTR + kc + lc + 4];
            }
#pragma unroll
            for (int ni = 0; ni < 8; ni++) {
                unsigned b0 = Bb[(kc + lc) * BSTR + wn + ni * 8 + lr];
                unsigned b1 = Bb[(kc + lc + 4) * BSTR + wn + ni * 8 + lr];
                mma_tf32(acc[0][ni], a[0], b0, b1);
                mma_tf32(acc[1][ni], a[1], b0, b1);
            }
        }
        __syncthreads();
    }

#pragma unroll
    for (int mi = 0; mi < 2; mi++) {
#pragma unroll
        for (int ni = 0; ni < 8; ni++) {
            int r0 = bm + wm + mi * 16 + lr;
            int col = bn + wn + ni * 8 + 2 * lc;
            float2 v0 = make_float2(acc[mi][ni][0], acc[mi][ni][1]);
            float2 v1 = make_float2(acc[mi][ni][2], acc[mi][ni][3]);
            float2 bb = *(const float2*)(bias + col);
            v0.x += bb.x; v0.y += bb.y;
            v1.x += bb.x; v1.y += bb.y;
            v0.x = v0.x > 0.f ? v0.x : SLOPE * v0.x;
            v0.y = v0.y > 0.f ? v0.y : SLOPE * v0.y;
            v1.x = v1.x > 0.f ? v1.x : SLOPE * v1.x;
            v1.y = v1.y > 0.f ? v1.y : SLOPE * v1.y;
            if (HOUT) {
                __half* C = (__half*)Cv;
                if (r0 < M)     *(__half2*)(C + (size_t)r0 * N + col) = __float22half2_rn(v0);
                if (r0 + 8 < M) *(__half2*)(C + (size_t)(r0 + 8) * N + col) = __float22half2_rn(v1);
            } else {
                float* C = (float*)Cv;
                if (r0 < M)     *(float2*)(C + (size_t)r0 * N + col) = v0;
                if (r0 + 8 < M) *(float2*)(C + (size_t)(r0 + 8) * N + col) = v1;
            }
        }
    }
}

// ---------------- FP16 tensor-core GEMM (layers 2,3) ---------------------------
// C[M,N] fp32 = A[M,K] (half, row-major) @ Wt[N,K]^T (half, K-major per row).
// Tile 128x128x32, 256 threads, 8 warps (4Mx2N), warp tile 32x64.
// mma.m16n8k16 f16 with fp32 accumulate; ldmatrix fragments; cp.async tiles.
#define HSTR 40   // half units per smem row: 32 + 8 pad (80B stride, conflict-free)

__device__ __forceinline__ void mma_f16(float* c, const unsigned* a, const unsigned* b) {
    asm("mma.sync.aligned.m16n8k16.row.col.f32.f16.f16.f32 "
        "{%0,%1,%2,%3}, {%4,%5,%6,%7}, {%8,%9}, {%0,%1,%2,%3};"
        : "+f"(c[0]), "+f"(c[1]), "+f"(c[2]), "+f"(c[3])
        : "r"(a[0]), "r"(a[1]), "r"(a[2]), "r"(a[3]), "r"(b[0]), "r"(b[1]));
}
__device__ __forceinline__ void ldsm4(unsigned* r, unsigned addr) {
    asm volatile("ldmatrix.sync.aligned.m8n8.x4.shared.b16 {%0,%1,%2,%3}, [%4];"
                 : "=r"(r[0]), "=r"(r[1]), "=r"(r[2]), "=r"(r[3]) : "r"(addr));
}

__global__ __launch_bounds__(256, 2) void gemm_f16(
    const __half* __restrict__ A, const __half* __restrict__ Wt,
    float* __restrict__ C, int M, int N, int K)
{
    __shared__ __half As[2][128 * HSTR];
    __shared__ __half Bs[2][128 * HSTR];
    const int tid = threadIdx.x;
    const int bm = blockIdx.y * 128;
    const int bn = blockIdx.x * 128;

    const int w = tid >> 5, lane = tid & 31;
    const int wm = (w & 3) * 32;
    const int wn = (w >> 2) * 64;
    const int lr = lane >> 2, lc = lane & 3;

    // ldmatrix per-lane offsets
    const int aRow = (lane & 7) + 8 * ((lane >> 3) & 1);
    const int aK   = 8 * (lane >> 4);
    const int bRow = (lane & 7) + 8 * (lane >> 4);
    const int bK   = 8 * ((lane >> 3) & 1);

    // loader: each tile row = 32 halves = 64B = 4 x 16B; 512 chunks, 2/thread
    const int lrow = tid >> 1;                 // not used directly; see chunk calc

    float acc[2][8][4];
#pragma unroll
    for (int mi = 0; mi < 2; mi++)
#pragma unroll
        for (int ni = 0; ni < 8; ni++)
#pragma unroll
            for (int q = 0; q < 4; q++) acc[mi][ni][q] = 0.f;

    auto issue = [&](int stage, int kt) {
#pragma unroll
        for (int i = 0; i < 2; i++) {
            int chunk = tid + 256 * i;
            int rr = chunk >> 2, cc = chunk & 3;
            const __half* g = A + (size_t)(bm + rr) * K + kt * 32 + cc * 8;
            unsigned d = sm32(&As[stage][rr * HSTR + cc * 8]);
            cp16(d, g, (bm + rr) < M);
        }
#pragma unroll
        for (int i = 0; i < 2; i++) {
            int chunk = tid + 256 * i;
            int rr = chunk >> 2, cc = chunk & 3;
            const __half* g = Wt + (size_t)(bn + rr) * K + kt * 32 + cc * 8;
            unsigned d = sm32(&Bs[stage][rr * HSTR + cc * 8]);
            cp16(d, g, true);
        }
    };

    issue(0, 0);
    CP_COMMIT();

    const int ktn = K / 32;
    for (int t = 0; t < ktn; t++) {
        if (t + 1 < ktn) {
            issue((t + 1) & 1, t + 1);
            CP_COMMIT();
            CP_WAIT1();
        } else {
            CP_WAIT0();
        }
        __syncthreads();
        const __half* Ab = As[t & 1];
        const __half* Bb = Bs[t & 1];
#pragma unroll
        for (int kc = 0; kc < 32; kc += 16) {
            unsigned a[2][4];
#pragma unroll
            for (int mi = 0; mi < 2; mi++)
                ldsm4(a[mi], sm32(Ab + (wm + mi * 16 + aRow) * HSTR + kc + aK));
            unsigned b[8][2];
#pragma unroll
            for (int pj = 0; pj < 4; pj++) {
                unsigned r4[4];
                ldsm4(r4, sm32(Bb + (wn + pj * 16 + bRow) * HSTR + kc + bK));
                b[pj * 2][0] = r4[0]; b[pj * 2][1] = r4[1];
                b[pj * 2 + 1][0] = r4[2]; b[pj * 2 + 1][1] = r4[3];
            }
#pragma unroll
            for (int ni = 0; ni < 8; ni++) {
                mma_f16(acc[0][ni], a[0], b[ni]);
                mma_f16(acc[1][ni], a[1], b[ni]);
            }
        }
        __syncthreads();
    }

#pragma unroll
    for (int mi = 0; mi < 2; mi++) {
#pragma unroll
        for (int ni = 0; ni < 8; ni++) {
            int r0 = bm + wm + mi * 16 + lr;
            int col = bn + wn + ni * 8 + 2 * lc;
            if (r0 < M)
                *(float2*)(C + (size_t)r0 * N + col) =
                    make_float2(acc[mi][ni][0], acc[mi][ni][1]);
            if (r0 + 8 < M)
                *(float2*)(C + (size_t)(r0 + 8) * N + col) =
                    make_float2(acc[mi][ni][2], acc[mi][ni][3]);
        }
    }
}

// ---------------- fused head: h3[64] -> Wp(32) -> leaky(Wf1(32)) -> Wf2(2) ----
__global__ __launch_bounds__(128) void head_kernel(
    const float* __restrict__ h3,
    const float* __restrict__ Wp, const float* __restrict__ bp,
    const float* __restrict__ Wf1, const float* __restrict__ bf1,
    const float* __restrict__ Wf2, const float* __restrict__ bf2,
    float* __restrict__ out, int n)
{
    __shared__ float sWp[64 * 32], sWf1[32 * 32], sWf2[64], sbp[32], sbf1[32], sbf2[2];
    for (int i = threadIdx.x; i < 64 * 32; i += blockDim.x) sWp[i] = Wp[i];
    for (int i = threadIdx.x; i < 32 * 32; i += blockDim.x) sWf1[i] = Wf1[i];
    for (int i = threadIdx.x; i < 64; i += blockDim.x) sWf2[i] = Wf2[i];
    if (threadIdx.x < 32) { sbp[threadIdx.x] = bp[threadIdx.x]; sbf1[threadIdx.x] = bf1[threadIdx.x]; }
    if (threadIdx.x < 2) sbf2[threadIdx.x] = bf2[threadIdx.x];
    __syncthreads();
    int nidx = blockIdx.x * blockDim.x + threadIdx.x;
    if (nidx >= n) return;

    float p[32];
#pragma unroll
    for (int j = 0; j < 32; j++) p[j] = sbp[j];
    const float* hx = h3 + (size_t)nidx * 64;
    for (int i = 0; i < 64; i++) {
        float xi = hx[i];
#pragma unroll
        for (int j = 0; j < 32; j++) p[j] = fmaf(xi, sWp[i * 32 + j], p[j]);
    }
    float q[32];
#pragma unroll
    for (int j = 0; j < 32; j++) q[j] = sbf1[j];
#pragma unroll
    for (int i = 0; i < 32; i++) {
#pragma unroll
        for (int j = 0; j < 32; j++) q[j] = fmaf(p[i], sWf1[i * 32 + j], q[j]);
    }
#pragma unroll
    for (int j = 0; j < 32; j++) q[j] = q[j] > 0.f ? q[j] : SLOPE * q[j];
    float o0 = sbf2[0], o1 = sbf2[1];
#pragma unroll
    for (int i = 0; i < 32; i++) { o0 = fmaf(q[i], sWf2[i * 2], o0); o1 = fmaf(q[i], sWf2[i * 2 + 1], o1); }
    out[(size_t)nidx * 2]     = o0;
    out[(size_t)nidx * 2 + 1] = o1;
}

// ---------------- launch ------------------------------------------------------
static inline int cdiv(long long a, int b) { return (int)((a + b - 1) / b); }

extern "C" void kernel_launch(void* const* d_in, const int* in_sizes, int n_in,
                              void* d_out, int out_size)
{
    const float* x   = (const float*)d_in[0];
    const int*   ei  = (const int*)d_in[1];
    // d_in[2..4] edge_attr/We/be: dead code in the reference
    const float* W1l = (const float*)d_in[5];
    const float* b1  = (const float*)d_in[6];
    const float* W1r = (const float*)d_in[7];
    const float* W2l = (const float*)d_in[8];
    const float* b2  = (const float*)d_in[9];
    const float* W2r = (const float*)d_in[10];
    const float* W3l = (const float*)d_in[11];
    const float* b3  = (const float*)d_in[12];
    const float* W3r = (const float*)d_in[13];
    const float* Wp  = (const float*)d_in[14];
    const float* bp  = (const float*)d_in[15];
    const float* Wf1 = (const float*)d_in[16];
    const float* bf1 = (const float*)d_in[17];
    const float* Wf2 = (const float*)d_in[18];
    const float* bf2 = (const float*)d_in[19];

    const int n  = in_sizes[0] / 128;   // 50000
    const int ne = in_sizes[1] / 2;     // 800000
    const int* src = ei;
    const int* dst = ei + ne;

    int *deg, *rowptr, *cursor, *csr;
    float *mean1, *c2, *c3, *h3;
    __half *wt2h, *wt3h, *h1h, *h2h;
    cudaGetSymbolAddress((void**)&deg,    g_deg);
    cudaGetSymbolAddress((void**)&rowptr, g_rowptr);
    cudaGetSymbolAddress((void**)&cursor, g_cursor);
    cudaGetSymbolAddress((void**)&csr,    g_csr);
    cudaGetSymbolAddress((void**)&mean1,  g_mean1);
    cudaGetSymbolAddress((void**)&c2,     g_c2);
    cudaGetSymbolAddress((void**)&c3,     g_c3);
    cudaGetSymbolAddress((void**)&h3,     g_h3);
    cudaGetSymbolAddress((void**)&wt2h,   g_wt2h);
    cudaGetSymbolAddress((void**)&wt3h,   g_wt3h);
    cudaGetSymbolAddress((void**)&h1h,    g_h1h);
    cudaGetSymbolAddress((void**)&h2h,    g_h2h);
    float* out = (float*)d_out;

    const int T = 256;
    const int gM = cdiv(n, 128);   // 391

    // ---- CSR build (kernel #4 = scatter; #5 = mean agg gets profiled slot -s5)
    cudaMemsetAsync(deg, 0, (size_t)n * sizeof(int));
    counti_kernel<<<cdiv(ne, T), T>>>(dst, deg, ne);                    // k1
    scan_kernel<<<1, 1024>>>(deg, rowptr, cursor, n);                   // k2
    scatter_kernel<<<cdiv(ne, T), T>>>(src, dst, cursor, csr, ne);      // k3
    // ---- layer-1 mean aggregation (unroll-4) — profiled slot (#4)
    csr_agg<32, false, false><<<cdiv(n, 8), T>>>(x, 32, rowptr, csr,
                                                 nullptr, 0, nullptr, mean1, 32, n); // k4
    prep_w<<<cdiv(512 * 512 + 128 * 256, T), T>>>(W2l, W2r, W3l, W3r);  // k5

    // ---- layer 1 (tf32): h1h = half(leaky([mean1|x] @ [W1l;W1r] + b1))
    gemm_tf32_l1<true><<<dim3(4, gM), T>>>(
        mean1, x, 128, W1l, W1r, h1h, b1, n, 512, 256);                 // k6

    // ---- layer 2 (fp16): c2 = [z2|r2] = h1h @ wt2h^T; h2h = half(leaky(mean+b2+r2))
    gemm_f16<<<dim3(4, gM), T>>>(h1h, wt2h, c2, n, 512, 512);           // k7
    csr_agg<64, true, true><<<cdiv(n, 8), T>>>(c2, 128, rowptr, csr,
                                               c2 + 256, 128, b2, h2h, 64, n);

    // ---- layer 3 (fp16): c3 = [z3|r3] = h2h @ wt3h^T; h3 = leaky(mean+b3+r3)
    gemm_f16<<<dim3(1, gM), T>>>(h2h, wt3h, c3, n, 128, 256);
    csr_agg<16, true, false><<<cdiv(n, 16), T>>>(c3, 32, rowptr, csr,
                                                 c3 + 64, 32, b3, h3, 16, n);

    // ---- fused head
    head_kernel<<<cdiv(n, 128), 128>>>(h3, Wp, bp, Wf1, bf1, Wf2, bf2, out, n);
}

// round 9
// speedup vs baseline: 4.6562x; 1.1511x over previous
#include <cuda_runtime.h>
#include <cuda_fp16.h>
#include <cstdint>

#define SLOPE 0.15f

static const int NN = 50000;
static const int NE = 800000;

// ---------------- device scratch ----------------------------------------------
__device__ int    g_deg[NN];
__device__ int    g_rowptr[NN + 1];
__device__ int    g_cursor[NN];
__device__ int    g_csr[NE];
__device__ __half g_xh[(size_t)NN * 128];
__device__ __half g_wt1h[512 * 256];          // [n][k] half, [W1l;W1r]^T (K-concat)
__device__ __half g_wt2h[512 * 512];          // [n][k] half, [W2l|W2r]^T
__device__ __half g_wt3h[128 * 256];          // [n][k] half, [W3l|W3r]^T
__device__ __half g_mean1h[(size_t)NN * 128];
__device__ __half g_h1h[(size_t)NN * 512];
__device__ __half g_c2h[(size_t)NN * 512];    // [z2 | r2] half
__device__ __half g_h2h[NN * 256];
__device__ __half g_c3h[NN * 128];            // [z3 | r3] half
__device__ float  g_h3[NN * 64];

__device__ __forceinline__ unsigned sm32(const void* p) {
    return (unsigned)__cvta_generic_to_shared(p);
}

// ---------------- CSR build ----------------------------------------------------
__global__ void counti_kernel(const int* __restrict__ dst, int* __restrict__ deg, int ne) {
    int e = blockIdx.x * blockDim.x + threadIdx.x;
    if (e < ne) atomicAdd(&deg[dst[e]], 1);
}

__global__ void scan_kernel(const int* __restrict__ deg, int* __restrict__ rowptr,
                            int* __restrict__ cursor, int n) {
    __shared__ int part[1024];
    const int t = threadIdx.x;
    const int chunk = (n + 1023) >> 10;
    int lo = t * chunk;
    int hi = lo + chunk; if (hi > n) hi = n;
    int s = 0;
    for (int i = lo; i < hi; i++) s += deg[i];
    part[t] = s;
    __syncthreads();
    for (int off = 1; off < 1024; off <<= 1) {
        int v = (t >= off) ? part[t - off] : 0;
        __syncthreads();
        part[t] += v;
        __syncthreads();
    }
    int base = (t == 0) ? 0 : part[t - 1];
    for (int i = lo; i < hi; i++) {
        rowptr[i] = base; cursor[i] = base;
        base += deg[i];
    }
    if (t == 1023) rowptr[n] = base;
}

__global__ void scatter_kernel(const int* __restrict__ src, const int* __restrict__ dst,
                               int* __restrict__ cursor, int* __restrict__ csr, int ne) {
    int e = blockIdx.x * blockDim.x + threadIdx.x;
    if (e < ne) {
        int p = atomicAdd(&cursor[dst[e]], 1);
        csr[p] = src[e];
    }
}

// ---------------- input conversion + weight prep --------------------------------
__global__ void cvt_x(const float* __restrict__ x, __half* __restrict__ xh, int n4) {
    int i = blockIdx.x * blockDim.x + threadIdx.x;
    if (i >= n4) return;
    float4 v = ((const float4*)x)[i];
    __half2* o = (__half2*)xh + (size_t)i * 2;
    o[0] = __float22half2_rn(make_float2(v.x, v.y));
    o[1] = __float22half2_rn(make_float2(v.z, v.w));
}

__global__ void prep_w(const float* __restrict__ W1l, const float* __restrict__ W1r,
                       const float* __restrict__ W2l, const float* __restrict__ W2r,
                       const float* __restrict__ W3l, const float* __restrict__ W3r) {
    int i = blockIdx.x * blockDim.x + threadIdx.x;
    if (i < 512 * 256) {               // wt1h: n in 0..511 over HID, k = concat dim
        int nn = i >> 8, k = i & 255;
        float v = (k < 128) ? W1l[k * 512 + nn] : W1r[(k - 128) * 512 + nn];
        g_wt1h[i] = __float2half_rn(v);
        return;
    }
    int j = i - 512 * 256;
    if (j < 512 * 512) {
        int nn = j >> 9, k = j & 511;
        float v = (nn < 256) ? W2l[k * 256 + nn] : W2r[k * 256 + (nn - 256)];
        g_wt2h[j] = __float2half_rn(v);
        return;
    }
    int l = j - 512 * 512;
    if (l < 128 * 256) {
        int nn = l >> 8, k = l & 255;
        float v = (nn < 64) ? W3l[k * 64 + nn] : W3r[k * 64 + (nn - 64)];
        g_wt3h[l] = __float2half_rn(v);
    }
}

// ---------------- CSR mean-aggregate (half in, fp32 accum, fused epilogue) -----
// feat/r are half; strides in units of 4 elements. OUTH: half out, else fp32.
template<int D4, bool FUSE, bool OUTH>
__global__ __launch_bounds__(256) void csr_agg(
    const __half* __restrict__ feat, int fstr4,
    const int* __restrict__ rowptr, const int* __restrict__ csr,
    const __half* __restrict__ r, int rstr4,
    const float* __restrict__ bias,
    void* __restrict__ outv, int ostr4, int n)
{
    const int L = (D4 < 32) ? D4 : 32;
    const int V = D4 / L;
    const int npb = 256 / L;
    int node = blockIdx.x * npb + threadIdx.x / L;
    int sl = threadIdx.x % L;
    if (node >= n) return;
    int beg = rowptr[node], end = rowptr[node + 1];
    const uint2* fH = (const uint2*)feat;   // 4 halves per uint2
    float4 acc[V];
#pragma unroll
    for (int v = 0; v < V; v++) acc[v] = make_float4(0.f, 0.f, 0.f, 0.f);

    auto addrow = [&](int s) {
#pragma unroll
        for (int v = 0; v < V; v++) {
            uint2 u = fH[(size_t)s * fstr4 + sl + v * L];
            float2 f0 = __half22float2(*(__half2*)&u.x);
            float2 f1 = __half22float2(*(__half2*)&u.y);
            acc[v].x += f0.x; acc[v].y += f0.y;
            acc[v].z += f1.x; acc[v].w += f1.y;
        }
    };
    int j = beg;
    for (; j + 4 <= end; j += 4) {
        int s0 = __ldg(&csr[j]),     s1 = __ldg(&csr[j + 1]);
        int s2 = __ldg(&csr[j + 2]), s3 = __ldg(&csr[j + 3]);
        addrow(s0); addrow(s1); addrow(s2); addrow(s3);
    }
    for (; j < end; j++) addrow(__ldg(&csr[j]));

    float inv = 1.0f / fmaxf((float)(end - beg), 1.0f);
#pragma unroll
    for (int v = 0; v < V; v++) {
        int c4 = sl + v * L;
        float4 o = make_float4(acc[v].x * inv, acc[v].y * inv, acc[v].z * inv, acc[v].w * inv);
        if (FUSE) {
            uint2 u = ((const uint2*)r)[(size_t)node * rstr4 + c4];
            float2 r0 = __half22float2(*(__half2*)&u.x);
            float2 r1 = __half22float2(*(__half2*)&u.y);
            float4 bb = ((const float4*)bias)[c4];
            o.x += bb.x + r0.x; o.y += bb.y + r0.y;
            o.z += bb.z + r1.x; o.w += bb.w + r1.y;
            o.x = o.x > 0.f ? o.x : SLOPE * o.x;
            o.y = o.y > 0.f ? o.y : SLOPE * o.y;
            o.z = o.z > 0.f ? o.z : SLOPE * o.z;
            o.w = o.w > 0.f ? o.w : SLOPE * o.w;
        }
        if (OUTH) {
            uint2 u;
            *(__half2*)&u.x = __float22half2_rn(make_float2(o.x, o.y));
            *(__half2*)&u.y = __float22half2_rn(make_float2(o.z, o.w));
            ((uint2*)outv)[(size_t)node * ostr4 + c4] = u;
        } else {
            ((float4*)outv)[(size_t)node * ostr4 + c4] = o;
        }
    }
}

// ---------------- FP16 tensor-core GEMM ----------------------------------------
// C[M,N] = A[M,K] (half row-major, optional K-concat A1|A2) @ Wt[N,K]^T (half).
// Tile 128x128x32, 256 threads, 8 warps (4Mx2N), mma.m16n8k16 f16, fp32 accum.
#define HSTR 40   // half units per smem row: 32 + 8 pad (80B stride)

__device__ __forceinline__ void mma_f16(float* c, const unsigned* a, const unsigned* b) {
    asm("mma.sync.aligned.m16n8k16.row.col.f32.f16.f16.f32 "
        "{%0,%1,%2,%3}, {%4,%5,%6,%7}, {%8,%9}, {%0,%1,%2,%3};"
        : "+f"(c[0]), "+f"(c[1]), "+f"(c[2]), "+f"(c[3])
        : "r"(a[0]), "r"(a[1]), "r"(a[2]), "r"(a[3]), "r"(b[0]), "r"(b[1]));
}
__device__ __forceinline__ void ldsm4(unsigned* r, unsigned addr) {
    asm volatile("ldmatrix.sync.aligned.m8n8.x4.shared.b16 {%0,%1,%2,%3}, [%4];"
                 : "=r"(r[0]), "=r"(r[1]), "=r"(r[2]), "=r"(r[3]) : "r"(addr));
}
__device__ __forceinline__ void cp16(unsigned saddr, const void* g, bool ok) {
    int sz = ok ? 16 : 0;
    asm volatile("cp.async.cg.shared.global [%0], [%1], 16, %2;"
                 :: "r"(saddr), "l"(g), "r"(sz));
}
#define CP_COMMIT() asm volatile("cp.async.commit_group;")
#define CP_WAIT1()  asm volatile("cp.async.wait_group 1;")
#define CP_WAIT0()  asm volatile("cp.async.wait_group 0;")

template<bool CONCAT, bool EPI, bool HOUT>
__global__ __launch_bounds__(256, 2) void gemm_f16(
    const __half* __restrict__ A1, const __half* __restrict__ A2, int K1,
    const __half* __restrict__ Wt, void* __restrict__ Cv,
    const float* __restrict__ bias, int M, int N, int K)
{
    __shared__ __half As[2][128 * HSTR];
    __shared__ __half Bs[2][128 * HSTR];
    const int tid = threadIdx.x;
    const int bm = blockIdx.y * 128;
    const int bn = blockIdx.x * 128;

    const int w = tid >> 5, lane = tid & 31;
    const int wm = (w & 3) * 32;
    const int wn = (w >> 2) * 64;
    const int lr = lane >> 2, lc = lane & 3;

    const int aRow = (lane & 7) + 8 * ((lane >> 3) & 1);
    const int aK   = 8 * (lane >> 4);
    const int bRow = (lane & 7) + 8 * (lane >> 4);
    const int bK   = 8 * ((lane >> 3) & 1);

    float acc[2][8][4];
#pragma unroll
    for (int mi = 0; mi < 2; mi++)
#pragma unroll
        for (int ni = 0; ni < 8; ni++)
#pragma unroll
            for (int q = 0; q < 4; q++) acc[mi][ni][q] = 0.f;

    const int K2 = K - K1;

    auto issue = [&](int stage, int kt) {
        int kg = kt * 32;
#pragma unroll
        for (int i = 0; i < 2; i++) {
            int chunk = tid + 256 * i;
            int rr = chunk >> 2, cc = chunk & 3;
            const __half* g;
            if (CONCAT) {
                g = (kg < K1) ? A1 + (size_t)(bm + rr) * K1 + kg + cc * 8
                              : A2 + (size_t)(bm + rr) * K2 + (kg - K1) + cc * 8;
            } else {
                g = A1 + (size_t)(bm + rr) * K + kg + cc * 8;
            }
            cp16(sm32(&As[stage][rr * HSTR + cc * 8]), g, (bm + rr) < M);
        }
#pragma unroll
        for (int i = 0; i < 2; i++) {
            int chunk = tid + 256 * i;
            int rr = chunk >> 2, cc = chunk & 3;
            const __half* g = Wt + (size_t)(bn + rr) * K + kg + cc * 8;
            cp16(sm32(&Bs[stage][rr * HSTR + cc * 8]), g, true);
        }
    };

    issue(0, 0);
    CP_COMMIT();

    const int ktn = K / 32;
    for (int t = 0; t < ktn; t++) {
        if (t + 1 < ktn) {
            issue((t + 1) & 1, t + 1);
            CP_COMMIT();
            CP_WAIT1();
        } else {
            CP_WAIT0();
        }
        __syncthreads();
        const __half* Ab = As[t & 1];
        const __half* Bb = Bs[t & 1];
#pragma unroll
        for (int kc = 0; kc < 32; kc += 16) {
            unsigned a[2][4];
#pragma unroll
            for (int mi = 0; mi < 2; mi++)
                ldsm4(a[mi], sm32(Ab + (wm + mi * 16 + aRow) * HSTR + kc + aK));
            unsigned b[8][2];
#pragma unroll
            for (int pj = 0; pj < 4; pj++) {
                unsigned r4[4];
                ldsm4(r4, sm32(Bb + (wn + pj * 16 + bRow) * HSTR + kc + bK));
                b[pj * 2][0] = r4[0]; b[pj * 2][1] = r4[1];
                b[pj * 2 + 1][0] = r4[2]; b[pj * 2 + 1][1] = r4[3];
            }
#pragma unroll
            for (int ni = 0; ni < 8; ni++) {
                mma_f16(acc[0][ni], a[0], b[ni]);
                mma_f16(acc[1][ni], a[1], b[ni]);
            }
        }
        __syncthreads();
    }

#pragma unroll
    for (int mi = 0; mi < 2; mi++) {
#pragma unroll
        for (int ni = 0; ni < 8; ni++) {
            int r0 = bm + wm + mi * 16 + lr;
            int col = bn + wn + ni * 8 + 2 * lc;
            float2 v0 = make_float2(acc[mi][ni][0], acc[mi][ni][1]);
            float2 v1 = make_float2(acc[mi][ni][2], acc[mi][ni][3]);
            if (EPI) {
                float2 bb = *(const float2*)(bias + col);
                v0.x += bb.x; v0.y += bb.y;
                v1.x += bb.x; v1.y += bb.y;
                v0.x = v0.x > 0.f ? v0.x : SLOPE * v0.x;
                v0.y = v0.y > 0.f ? v0.y : SLOPE * v0.y;
                v1.x = v1.x > 0.f ? v1.x : SLOPE * v1.x;
                v1.y = v1.y > 0.f ? v1.y : SLOPE * v1.y;
            }
            if (HOUT) {
                __half* C = (__half*)Cv;
                if (r0 < M)     *(__half2*)(C + (size_t)r0 * N + col) = __float22half2_rn(v0);
                if (r0 + 8 < M) *(__half2*)(C + (size_t)(r0 + 8) * N + col) = __float22half2_rn(v1);
            } else {
                float* C = (float*)Cv;
                if (r0 < M)     *(float2*)(C + (size_t)r0 * N + col) = v0;
                if (r0 + 8 < M) *(float2*)(C + (size_t)(r0 + 8) * N + col) = v1;
            }
        }
    }
}

// ---------------- fused head: h3[64] -> Wp(32) -> leaky(Wf1(32)) -> Wf2(2) ----
__global__ __launch_bounds__(128) void head_kernel(
    const float* __restrict__ h3,
    const float* __restrict__ Wp, const float* __restrict__ bp,
    const float* __restrict__ Wf1, const float* __restrict__ bf1,
    const float* __restrict__ Wf2, const float* __restrict__ bf2,
    float* __restrict__ out, int n)
{
    __shared__ float sWp[64 * 32], sWf1[32 * 32], sWf2[64], sbp[32], sbf1[32], sbf2[2];
    for (int i = threadIdx.x; i < 64 * 32; i += blockDim.x) sWp[i] = Wp[i];
    for (int i = threadIdx.x; i < 32 * 32; i += blockDim.x) sWf1[i] = Wf1[i];
    for (int i = threadIdx.x; i < 64; i += blockDim.x) sWf2[i] = Wf2[i];
    if (threadIdx.x < 32) { sbp[threadIdx.x] = bp[threadIdx.x]; sbf1[threadIdx.x] = bf1[threadIdx.x]; }
    if (threadIdx.x < 2) sbf2[threadIdx.x] = bf2[threadIdx.x];
    __syncthreads();
    int nidx = blockIdx.x * blockDim.x + threadIdx.x;
    if (nidx >= n) return;

    float p[32];
#pragma unroll
    for (int j = 0; j < 32; j++) p[j] = sbp[j];
    const float* hx = h3 + (size_t)nidx * 64;
    for (int i = 0; i < 64; i++) {
        float xi = hx[i];
#pragma unroll
        for (int j = 0; j < 32; j++) p[j] = fmaf(xi, sWp[i * 32 + j], p[j]);
    }
    float q[32];
#pragma unroll
    for (int j = 0; j < 32; j++) q[j] = sbf1[j];
#pragma unroll
    for (int i = 0; i < 32; i++) {
#pragma unroll
        for (int j = 0; j < 32; j++) q[j] = fmaf(p[i], sWf1[i * 32 + j], q[j]);
    }
#pragma unroll
    for (int j = 0; j < 32; j++) q[j] = q[j] > 0.f ? q[j] : SLOPE * q[j];
    float o0 = sbf2[0], o1 = sbf2[1];
#pragma unroll
    for (int i = 0; i < 32; i++) { o0 = fmaf(q[i], sWf2[i * 2], o0); o1 = fmaf(q[i], sWf2[i * 2 + 1], o1); }
    out[(size_t)nidx * 2]     = o0;
    out[(size_t)nidx * 2 + 1] = o1;
}

// ---------------- launch ------------------------------------------------------
static inline int cdiv(long long a, int b) { return (int)((a + b - 1) / b); }

extern "C" void kernel_launch(void* const* d_in, const int* in_sizes, int n_in,
                              void* d_out, int out_size)
{
    const float* x   = (const float*)d_in[0];
    const int*   ei  = (const int*)d_in[1];
    // d_in[2..4] edge_attr/We/be: dead code in the reference
    const float* W1l = (const float*)d_in[5];
    const float* b1  = (const float*)d_in[6];
    const float* W1r = (const float*)d_in[7];
    const float* W2l = (const float*)d_in[8];
    const float* b2  = (const float*)d_in[9];
    const float* W2r = (const float*)d_in[10];
    const float* W3l = (const float*)d_in[11];
    const float* b3  = (const float*)d_in[12];
    const float* W3r = (const float*)d_in[13];
    const float* Wp  = (const float*)d_in[14];
    const float* bp  = (const float*)d_in[15];
    const float* Wf1 = (const float*)d_in[16];
    const float* bf1 = (const float*)d_in[17];
    const float* Wf2 = (const float*)d_in[18];
    const float* bf2 = (const float*)d_in[19];

    const int n  = in_sizes[0] / 128;   // 50000
    const int ne = in_sizes[1] / 2;     // 800000
    const int* src = ei;
    const int* dst = ei + ne;

    int *deg, *rowptr, *cursor, *csr;
    float *h3;
    __half *xh, *wt1h, *wt2h, *wt3h, *mean1h, *h1h, *c2h, *h2h, *c3h;
    cudaGetSymbolAddress((void**)&deg,    g_deg);
    cudaGetSymbolAddress((void**)&rowptr, g_rowptr);
    cudaGetSymbolAddress((void**)&cursor, g_cursor);
    cudaGetSymbolAddress((void**)&csr,    g_csr);
    cudaGetSymbolAddress((void**)&xh,     g_xh);
    cudaGetSymbolAddress((void**)&wt1h,   g_wt1h);
    cudaGetSymbolAddress((void**)&wt2h,   g_wt2h);
    cudaGetSymbolAddress((void**)&wt3h,   g_wt3h);
    cudaGetSymbolAddress((void**)&mean1h, g_mean1h);
    cudaGetSymbolAddress((void**)&h1h,    g_h1h);
    cudaGetSymbolAddress((void**)&c2h,    g_c2h);
    cudaGetSymbolAddress((void**)&h2h,    g_h2h);
    cudaGetSymbolAddress((void**)&c3h,    g_c3h);
    cudaGetSymbolAddress((void**)&h3,     g_h3);
    float* out = (float*)d_out;

    const int T = 256;
    const int gM = cdiv(n, 128);   // 391

    // ---- CSR build + conversions
    cudaMemsetAsync(deg, 0, (size_t)n * sizeof(int));
    counti_kernel<<<cdiv(ne, T), T>>>(dst, deg, ne);
    scan_kernel<<<1, 1024>>>(deg, rowptr, cursor, n);
    cvt_x<<<cdiv((long long)n * 32, T), T>>>(x, xh, n * 32);
    scatter_kernel<<<cdiv(ne, T), T>>>(src, dst, cursor, csr, ne);
    prep_w<<<cdiv(512 * 256 + 512 * 512 + 128 * 256, T), T>>>(W1l, W1r, W2l, W2r, W3l, W3r);

    // ---- layer 1 (fp16): mean1h = mean_csr(xh); h1h = leaky([mean1h|xh]@wt1h^T + b1)
    csr_agg<32, false, true><<<cdiv(n, 8), T>>>(xh, 32, rowptr, csr,
                                                nullptr, 0, nullptr, mean1h, 32, n);
    gemm_f16<true, true, true><<<dim3(4, gM), T>>>(
        mean1h, xh, 128, wt1h, h1h, b1, n, 512, 256);

    // ---- layer 2 (fp16): c2h = [z2|r2] = h1h @ wt2h^T; h2h = leaky(mean+b2+r2)
    gemm_f16<false, false, true><<<dim3(4, gM), T>>>(
        h1h, nullptr, 0, wt2h, c2h, nullptr, n, 512, 512);
    csr_agg<64, true, true><<<cdiv(n, 8), T>>>(c2h, 128, rowptr, csr,
                                               c2h + 256, 128, b2, h2h, 64, n);

    // ---- layer 3 (fp16): c3h = [z3|r3] = h2h @ wt3h^T; h3 = leaky(mean+b3+r3)
    gemm_f16<false, false, true><<<dim3(1, gM), T>>>(
        h2h, nullptr, 0, wt3h, c3h, nullptr, n, 128, 256);
    csr_agg<16, true, false><<<cdiv(n, 16), T>>>(c3h, 32, rowptr, csr,
                                                 c3h + 64, 32, b3, h3, 16, n);

    // ---- fused head
    head_kernel<<<cdiv(n, 128), 128>>>(h3, Wp, bp, Wf1, bf1, Wf2, bf2, out, n);
}